// round 15
// baseline (speedup 1.0000x reference)
#include <cuda_runtime.h>
#include <cuda_bf16.h>
#include <math.h>

typedef unsigned long long u64;
typedef unsigned int u32;

#define B_MAX 4
#define N_IN 25089      // 1 + 8*56*56
#define T_IN 8
#define H_IN 56
#define W_IN 56
#define QT 8
#define QH 28
#define QW 28
#define QN 6273         // 1 + 8*28*28
#define KT 8
#define KH 7
#define KW 7
#define KN 393          // 1 + 8*7*7
#define KNP 448         // padded key count
#define NKV 3201        // 1 + 8*20*20 gathered tokens per batch
#define ATTN_SCALE 0.102062072615965745f   // 1/sqrt(96)

// ---------------- scratch (device globals; no allocation) ----------------
__device__ float g_q [(size_t)B_MAX * N_IN * 192];
__device__ float g_k [(size_t)B_MAX * NKV * 192];
__device__ float g_v [(size_t)B_MAX * NKV * 192];
__device__ float g_qp[(size_t)B_MAX * 2 * QN * 96];
// bf16 hi/lo pre-split tensors
__device__ __nv_bfloat16 g_xh[(size_t)B_MAX * N_IN * 96];
__device__ __nv_bfloat16 g_xl[(size_t)B_MAX * N_IN * 96];
__device__ __nv_bfloat16 g_wh[576 * 96];
__device__ __nv_bfloat16 g_wl[576 * 96];
__device__ __nv_bfloat16 g_pwh[192 * 192];
__device__ __nv_bfloat16 g_pwl[192 * 192];
__device__ __nv_bfloat16 g_aoh[(size_t)B_MAX * QN * 192];
__device__ __nv_bfloat16 g_aol[(size_t)B_MAX * QN * 192];
// pooled q pre-split (unscaled)
__device__ __nv_bfloat16 g_qph[(size_t)B_MAX * 2 * QN * 96];
__device__ __nv_bfloat16 g_qpl[(size_t)B_MAX * 2 * QN * 96];
// extended pooled K (128 cols: 96 scaled ch + 22 onehot + mask + pad) and pooled V
__device__ __nv_bfloat16 g_keh[(size_t)B_MAX * 2 * KNP * 128];
__device__ __nv_bfloat16 g_kel[(size_t)B_MAX * 2 * KNP * 128];
__device__ __nv_bfloat16 g_vph[(size_t)B_MAX * 2 * KN * 96];
__device__ __nv_bfloat16 g_vpl[(size_t)B_MAX * 2 * KN * 96];

// ---------------- helpers ----------------
__device__ __forceinline__ int hw_from_idx(int i) {
    return (i < 2) ? i : 7 + ((i - 2) / 3) * 8 + ((i - 2) % 3);
}
__device__ __forceinline__ u32 smem_u32(const void* p) {
    u32 a;
    asm("{ .reg .u64 t; cvta.to.shared.u64 t, %1; cvt.u32.u64 %0, t; }" : "=r"(a) : "l"(p));
    return a;
}
__device__ __forceinline__ u64 fma2o(u64 a, u64 b, u64 c) {
    u64 d; asm("fma.rn.f32x2 %0, %1, %2, %3;" : "=l"(d) : "l"(a), "l"(b), "l"(c)); return d;
}
__device__ __forceinline__ u64 add2(u64 a, u64 b) {
    u64 d; asm("add.rn.f32x2 %0, %1, %2;" : "=l"(d) : "l"(a), "l"(b)); return d;
}
__device__ __forceinline__ u64 mul2(u64 a, u64 b) {
    u64 d; asm("mul.rn.f32x2 %0, %1, %2;" : "=l"(d) : "l"(a), "l"(b)); return d;
}
__device__ __forceinline__ u64 dupf(float v) {
    u64 r; asm("mov.b64 %0, {%1, %1};" : "=l"(r) : "f"(v)); return r;
}
__device__ __forceinline__ float2 u2f(u64 v) {
    float2 r; asm("mov.b64 {%0, %1}, %2;" : "=f"(r.x), "=f"(r.y) : "l"(v)); return r;
}
__device__ __forceinline__ u64 pk2(float a, float b) {
    u64 r; asm("mov.b64 %0, {%1, %2};" : "=l"(r) : "f"(a), "f"(b)); return r;
}
// packed fast exp: e^x for two lanes, poly deg-4, rel err ~4e-5
__device__ __forceinline__ u64 fexp2(float a, float b) {
    u64 x2 = pk2(a, b);
    u64 t2 = fma2o(x2, dupf(1.4426950408889634f), dupf(12582912.f));
    u64 n2 = add2(t2, dupf(-12582912.f));
    u64 r2 = fma2o(n2, dupf(-0.6931471805599453f), x2);
    u64 p2 = fma2o(r2, dupf(4.1666667e-2f), dupf(1.6666667e-1f));
    p2 = fma2o(p2, r2, dupf(0.5f));
    p2 = fma2o(p2, r2, dupf(1.0f));
    p2 = fma2o(p2, r2, dupf(1.0f));
    u32 tl = (u32)t2, th = (u32)(t2 >> 32);
    u32 sl = (tl << 23) + 0x3f800000u;
    u32 sh = (th << 23) + 0x3f800000u;
    u64 s2 = ((u64)sh << 32) | (u64)sl;
    return mul2(p2, s2);
}

// ---------------- mma.sync helpers ----------------
__device__ __forceinline__ void ldm_x4(u32* r, u32 addr) {
    asm volatile("ldmatrix.sync.aligned.m8n8.x4.shared.b16 {%0,%1,%2,%3}, [%4];"
        : "=r"(r[0]), "=r"(r[1]), "=r"(r[2]), "=r"(r[3]) : "r"(addr));
}
__device__ __forceinline__ void ldm_x4t(u32* r, u32 addr) {
    asm volatile("ldmatrix.sync.aligned.m8n8.x4.trans.shared.b16 {%0,%1,%2,%3}, [%4];"
        : "=r"(r[0]), "=r"(r[1]), "=r"(r[2]), "=r"(r[3]) : "r"(addr));
}
__device__ __forceinline__ void mma_bf16(float* c, const u32* a, const u32* b) {
    asm volatile("mma.sync.aligned.m16n8k16.row.col.f32.bf16.bf16.f32 "
        "{%0,%1,%2,%3}, {%4,%5,%6,%7}, {%8,%9}, {%0,%1,%2,%3};"
        : "+f"(c[0]), "+f"(c[1]), "+f"(c[2]), "+f"(c[3])
        : "r"(a[0]), "r"(a[1]), "r"(a[2]), "r"(a[3]), "r"(b[0]), "r"(b[1]));
}
__device__ __forceinline__ void split_store(__nv_bfloat16* hi, __nv_bfloat16* lo,
                                            size_t idx, float2 v) {
    __nv_bfloat162 h = __floats2bfloat162_rn(v.x, v.y);
    __nv_bfloat162 l = __floats2bfloat162_rn(v.x - __bfloat162float(h.x),
                                             v.y - __bfloat162float(h.y));
    *(__nv_bfloat162*)(hi + idx) = h;
    *(__nv_bfloat162*)(lo + idx) = l;
}
__device__ __forceinline__ u32 pack_hi(float a, float b, u32& lo) {
    __nv_bfloat162 h = __floats2bfloat162_rn(a, b);
    __nv_bfloat162 l = __floats2bfloat162_rn(a - __bfloat162float(h.x),
                                             b - __bfloat162float(h.y));
    lo = *(u32*)&l;
    return *(u32*)&h;
}
__device__ __forceinline__ void cpa16(u32 dst, const void* src, int srcsize) {
    asm volatile("cp.async.cg.shared.global [%0], [%1], 16, %2;"
        :: "r"(dst), "l"(src), "r"(srcsize));
}
#define CP_COMMIT() asm volatile("cp.async.commit_group;" ::: "memory")
#define CP_WAIT0()  asm volatile("cp.async.wait_group 0;" ::: "memory")
#define CP_WAIT1()  asm volatile("cp.async.wait_group 1;" ::: "memory")

// ---------------- presplit: x / qkv_w / proj_w -> bf16 hi/lo ----------------
__global__ void presplit_kernel(const float* __restrict__ x,
                                const float* __restrict__ qkv_w,
                                const float* __restrict__ proj_w, int nx)
{
    int i = blockIdx.x * 256 + threadIdx.x;
    const int nqkv = 576 * 96 / 2;
    const int nproj = 192 * 192 / 2;
    const float* src;
    __nv_bfloat16 *dh, *dl;
    int off;
    if (i < nx)                   { src = x;      dh = g_xh;  dl = g_xl;  off = i; }
    else if (i < nx + nqkv)       { src = qkv_w;  dh = g_wh;  dl = g_wl;  off = i - nx; }
    else if (i < nx + nqkv + nproj) { src = proj_w; dh = g_pwh; dl = g_pwl; off = i - nx - nqkv; }
    else return;
    float2 v = ((const float2*)src)[off];
    split_store(dh, dl, (size_t)(2 * off), v);
}

// ============================================================================
// cp.async double-buffered bf16 tensor-core GEMM (unchanged)
// ============================================================================
#define STG_BYTES 51200
#define STG_AL 10240
#define STG_B  20480
#define STG_BL 15360
#define GEMM_SMEM (2 * STG_BYTES)

__global__ void __launch_bounds__(256) gemm_bf16(
    const float* __restrict__ bias_all, float* __restrict__ outp,
    int Mq, int Mkv, int K, int nbQ, int nbKV, int fused)
{
    extern __shared__ char sm[];
    u32 smb = smem_u32(sm);

    int tid = threadIdx.x;
    int warp = tid >> 5, lane = tid & 31;
    int rm = (warp & 3) * 32;
    int cn = (warp >> 2) * 96;

    const __nv_bfloat16 *Asrc_h, *Asrc_l, *Bsrc_h, *Bsrc_l;
    const float* bp;
    float* out;
    int r0, Mloc;
    bool gather = false;
    if (!fused) {
        Asrc_h = g_aoh; Asrc_l = g_aol; Bsrc_h = g_pwh; Bsrc_l = g_pwl;
        bp = bias_all; out = outp; r0 = blockIdx.x * 128; Mloc = Mq;
    } else if ((int)blockIdx.x < nbQ) {
        Asrc_h = g_xh; Asrc_l = g_xl; Bsrc_h = g_wh; Bsrc_l = g_wl;
        bp = bias_all; out = (float*)g_q; r0 = blockIdx.x * 128; Mloc = Mq;
    } else {
        int t = blockIdx.x - nbQ;
        int sel = t / nbKV, bx2 = t - sel * nbKV;
        gather = true;
        Asrc_h = g_xh; Asrc_l = g_xl;
        Bsrc_h = g_wh + (size_t)(1 + sel) * 192 * 96;
        Bsrc_l = g_wl + (size_t)(1 + sel) * 192 * 96;
        bp = bias_all + (1 + sel) * 192;
        out = sel ? (float*)g_v : (float*)g_k;
        r0 = bx2 * 128; Mloc = Mkv;
    }

    size_t aoff[4];
    int asz[4];
    #pragma unroll
    for (int k4 = 0; k4 < 4; ++k4) {
        int l = tid + k4 * 256;
        int row = l >> 3;
        int r = r0 + row;
        if (r < Mloc) {
            asz[k4] = 16;
            if (gather) {
                int b = r / NKV, ci = r - b * NKV;
                int n = 0;
                if (ci > 0) {
                    int cc = ci - 1;
                    int it = cc / 400, rem = cc - it * 400;
                    int h = hw_from_idx(rem / 20), wv = hw_from_idx(rem % 20);
                    n = 1 + (it * H_IN + h) * W_IN + wv;
                }
                aoff[k4] = ((size_t)b * N_IN + n) * 96;
            } else {
                aoff[k4] = (size_t)r * K;
            }
        } else { aoff[k4] = 0; asz[k4] = 0; }
    }

    float C[2][12][4];
    #pragma unroll
    for (int mt = 0; mt < 2; ++mt)
        #pragma unroll
        for (int nt = 0; nt < 12; ++nt)
            #pragma unroll
            for (int i = 0; i < 4; ++i) C[mt][nt][i] = 0.f;

    int nch = K / 32;

    #define ISSUE_CHUNK(c_, st_) do {                                          \
        int kc = (c_) * 32;                                                    \
        u32 sb = smb + (st_) * STG_BYTES;                                      \
        _Pragma("unroll")                                                      \
        for (int k4 = 0; k4 < 4; ++k4) {                                       \
            int l = tid + k4 * 256;                                            \
            int row = l >> 3, hl = (l >> 2) & 1, seg = l & 3;                  \
            u32 dst = sb + hl * STG_AL + (u32)row * 80u + (u32)seg * 16u;      \
            const __nv_bfloat16* s0 = hl ? Asrc_l : Asrc_h;                    \
            cpa16(dst, s0 + aoff[k4] + kc + seg * 8, asz[k4]);                 \
        }                                                                      \
        _Pragma("unroll")                                                      \
        for (int k6 = 0; k6 < 6; ++k6) {                                       \
            int l = tid + k6 * 256;                                            \
            int row = l >> 3, hl = (l >> 2) & 1, seg = l & 3;                  \
            u32 dst = sb + STG_B + hl * STG_BL + (u32)row * 80u + (u32)seg * 16u; \
            const __nv_bfloat16* s0 = hl ? Bsrc_l : Bsrc_h;                    \
            cpa16(dst, s0 + (size_t)row * K + kc + seg * 8, 16);               \
        }                                                                      \
        CP_COMMIT();                                                           \
    } while (0)

    ISSUE_CHUNK(0, 0);

    for (int c = 0; c < nch; ++c) {
        int st = c & 1;
        if (c + 1 < nch) {
            ISSUE_CHUNK(c + 1, st ^ 1);
            CP_WAIT1();
        } else {
            CP_WAIT0();
        }
        __syncthreads();

        u32 sb = smb + st * STG_BYTES;
        #pragma unroll
        for (int ks = 0; ks < 2; ++ks) {
            int k0 = ks * 16;
            u32 ah[2][4], al[2][4];
            #pragma unroll
            for (int mt = 0; mt < 2; ++mt) {
                u32 off = (u32)(rm + mt * 16 + (lane & 15)) * 80u
                        + (u32)(k0 + ((lane >> 4) << 3)) * 2u;
                ldm_x4(ah[mt], sb + off);
                ldm_x4(al[mt], sb + STG_AL + off);
            }
            #pragma unroll
            for (int np = 0; np < 6; ++np) {
                u32 off = (u32)(cn + np * 16 + ((lane >> 4) << 3) + (lane & 7)) * 80u
                        + (u32)(k0 + (((lane >> 3) & 1) << 3)) * 2u;
                u32 bh4[4], bl4[4];
                ldm_x4(bh4, sb + STG_B + off);
                ldm_x4(bl4, sb + STG_B + STG_BL + off);
                #pragma unroll
                for (int mt = 0; mt < 2; ++mt) {
                    mma_bf16(C[mt][2 * np],     ah[mt], bh4);
                    mma_bf16(C[mt][2 * np],     ah[mt], bl4);
                    mma_bf16(C[mt][2 * np],     al[mt], bh4);
                    mma_bf16(C[mt][2 * np + 1], ah[mt], bh4 + 2);
                    mma_bf16(C[mt][2 * np + 1], ah[mt], bl4 + 2);
                    mma_bf16(C[mt][2 * np + 1], al[mt], bh4 + 2);
                }
            }
        }
        __syncthreads();
    }

    int gr = lane >> 2;
    int gc = (lane & 3) * 2;
    #pragma unroll
    for (int mt = 0; mt < 2; ++mt) {
        int row0 = r0 + rm + mt * 16 + gr;
        int row1 = row0 + 8;
        #pragma unroll
        for (int nt = 0; nt < 12; ++nt) {
            int col = cn + nt * 8 + gc;
            float b0 = bp[col], b1 = bp[col + 1];
            if (row0 < Mloc) {
                float2 o = make_float2(C[mt][nt][0] + b0, C[mt][nt][1] + b1);
                *(float2*)&out[(size_t)row0 * 192 + col] = o;
            }
            if (row1 < Mloc) {
                float2 o = make_float2(C[mt][nt][2] + b0, C[mt][nt][3] + b1);
                *(float2*)&out[(size_t)row1 * 192 + col] = o;
            }
        }
    }
}

// ---------------- LN helper (96 threads) ----------------
__device__ __forceinline__ float ln96(float val, const float* gg, const float* bb, int c,
                                      float* p1, float* p2, float* mv)
{
    float s1 = val, s2 = val * val;
    #pragma unroll
    for (int off = 16; off > 0; off >>= 1) {
        s1 += __shfl_xor_sync(0xffffffffu, s1, off);
        s2 += __shfl_xor_sync(0xffffffffu, s2, off);
    }
    int wid = c >> 5, lane = c & 31;
    if (lane == 0) { p1[wid] = s1; p2[wid] = s2; }
    __syncthreads();
    if (c == 0) {
        float t1 = p1[0] + p1[1] + p1[2];
        float t2 = p2[0] + p2[1] + p2[2];
        float mean = t1 / 96.f;
        float var  = t2 / 96.f - mean * mean;
        mv[0] = mean; mv[1] = rsqrtf(var + 1e-5f);
    }
    __syncthreads();
    return (val - mv[0]) * mv[1] * gg[c] + bb[c];
}

// ---------------- merged pool kernel ----------------
__global__ void pool_all_kernel(
    const float* __restrict__ cwq, const float* __restrict__ ggq, const float* __restrict__ bbq,
    const float* __restrict__ cwk, const float* __restrict__ ggk, const float* __restrict__ bbk,
    const float* __restrict__ cwv, const float* __restrict__ ggv, const float* __restrict__ bbv,
    int nSpatial, int nPQ, int nPKV)
{
    __shared__ float p1[3], p2[3], mv[2];
    int bx = blockIdx.x;
    int c = threadIdx.x;

    if (bx < nPQ) {
        int o = bx;
        if (o >= nSpatial) {
            int idx = o - nSpatial;
            int head = idx & 1, b = idx >> 1;
            float val = g_q[((size_t)b * N_IN) * 192 + head * 96 + c];
            float outv = ln96(val, ggq, bbq, c, p1, p2, mv);
            size_t oi = ((size_t)((b * 2 + head) * QN)) * 96 + c;
            g_qp[oi] = outv;
            __nv_bfloat16 h = __float2bfloat16(outv);
            g_qph[oi] = h;
            g_qpl[oi] = __float2bfloat16(outv - __bfloat162float(h));
            return;
        }
        int w2 = o % QW;
        int h2 = (o / QW) % QH;
        int head = (o / (QW * QH)) & 1;
        int b = o / (QW * QH * 2);

        float wreg[27];
        #pragma unroll
        for (int t = 0; t < 27; ++t) wreg[t] = cwq[c * 27 + t];

        float ps[8][3];
        #pragma unroll
        for (int it = 0; it < 8; ++it)
            #pragma unroll
            for (int d = 0; d < 3; ++d) ps[it][d] = 0.f;

        const float* base = g_q + ((size_t)(b * N_IN + 1)) * 192 + head * 96 + c;
        #pragma unroll
        for (int dh = 0; dh < 3; ++dh) {
            int ih = 2 * h2 - 1 + dh;
            if (ih < 0 || ih >= H_IN) continue;
            #pragma unroll
            for (int dw = 0; dw < 3; ++dw) {
                int iw = 2 * w2 - 1 + dw;
                if (iw < 0 || iw >= W_IN) continue;
                float w0 = wreg[(0 * 3 + dh) * 3 + dw];
                float w1 = wreg[(1 * 3 + dh) * 3 + dw];
                float w2r = wreg[(2 * 3 + dh) * 3 + dw];
                #pragma unroll
                for (int it = 0; it < 8; ++it) {
                    int tok = (it * H_IN + ih) * W_IN + iw;
                    float v = base[(size_t)tok * 192];
                    ps[it][0] = fmaf(w0, v, ps[it][0]);
                    ps[it][1] = fmaf(w1, v, ps[it][1]);
                    ps[it][2] = fmaf(w2r, v, ps[it][2]);
                }
            }
        }
        for (int t2 = 0; t2 < QT; ++t2) {
            float s = ps[t2][1];
            if (t2 > 0) s += ps[t2 - 1][0];
            if (t2 < 7) s += ps[t2 + 1][2];
            float outv = ln96(s, ggq, bbq, c, p1, p2, mv);
            int n = 1 + (t2 * QH + h2) * QW + w2;
            size_t oi = ((size_t)((b * 2 + head) * QN) + n) * 96 + c;
            g_qp[oi] = outv;
            __nv_bfloat16 h = __float2bfloat16(outv);
            g_qph[oi] = h;
            g_qpl[oi] = __float2bfloat16(outv - __bfloat162float(h));
            __syncthreads();
        }
        return;
    }

    int t = bx - nPQ;
    int whichV = t / nPKV;
    int o = t - whichV * nPKV;
    const float* cw = whichV ? cwv : cwk;
    const float* gg = whichV ? ggv : ggk;
    const float* bb = whichV ? bbv : bbk;
    int n    = o % KNP;
    int head = (o / KNP) & 1;
    int b    = o / (KNP * 2);
    int bh   = b * 2 + head;

    if (n >= KN) {
        if (whichV) return;
        size_t rb = ((size_t)bh * KNP + n) * 128;
        __nv_bfloat16 z = __float2bfloat16(0.f);
        g_keh[rb + c] = z; g_kel[rb + c] = z;
        if (c < 32) {
            g_keh[rb + 96 + c] = __float2bfloat16((c == 22) ? 1.f : 0.f);
            g_kel[rb + 96 + c] = z;
        }
        return;
    }

    const float* src = whichV ? g_v : g_k;
    float val;
    if (n == 0) {
        val = src[((size_t)b * NKV) * 192 + head * 96 + c];
    } else {
        int tn  = n - 1;
        int t2  = tn / (KH * KW);
        int rem = tn % (KH * KW);
        int h2  = rem / KW, w2 = rem % KW;
        float s = 0.f;
        #pragma unroll
        for (int dt = 0; dt < 3; ++dt) {
            int it = t2 + dt - 1;
            if (it < 0 || it >= T_IN) continue;
            #pragma unroll
            for (int dh = 0; dh < 3; ++dh) {
                int ih = h2 * 8 + dh - 1;
                if (ih < 0 || ih >= H_IN) continue;
                #pragma unroll
                for (int dw = 0; dw < 3; ++dw) {
                    int iw = w2 * 8 + dw - 1;
                    if (iw < 0 || iw >= W_IN) continue;
                    int hi2 = (ih <= 1) ? ih : 2 + ((ih - 7) >> 3) * 3 + ((ih - 7) & 7);
                    int wi2 = (iw <= 1) ? iw : 2 + ((iw - 7) >> 3) * 3 + ((iw - 7) & 7);
                    int ci = 1 + (it * 20 + hi2) * 20 + wi2;
                    s = fmaf(cw[c * 27 + (dt * 3 + dh) * 3 + dw],
                             src[((size_t)(b * NKV + ci)) * 192 + head * 96 + c], s);
                }
            }
        }
        val = s;
    }
    float outv = ln96(val, gg, bb, c, p1, p2, mv);
    if (whichV) {
        size_t oidx = ((size_t)bh * KN + n) * 96 + c;
        __nv_bfloat16 h = __float2bfloat16(outv);
        g_vph[oidx] = h;
        g_vpl[oidx] = __float2bfloat16(outv - __bfloat162float(h));
    } else {
        // fold ATTN_SCALE into K channels
        float sv = outv * ATTN_SCALE;
        size_t rb = ((size_t)bh * KNP + n) * 128;
        __nv_bfloat16 h = __float2bfloat16(sv);
        g_keh[rb + c] = h;
        g_kel[rb + c] = __float2bfloat16(sv - __bfloat162float(h));
        if (c < 32) {
            float ev = 0.f;
            if (n > 0 && c < 22) {
                int kk = n - 1, kt = kk / 49, rm = kk % 49;
                int rh = rm / 7, rw = rm % 7;
                if (c == kt || c == 8 + rh || c == 15 + rw) ev = 1.f;
            }
            g_keh[rb + 96 + c] = __float2bfloat16(ev);
            g_kel[rb + 96 + c] = __float2bfloat16(0.f);
        }
    }
}

// ============================================================================
// FA2 attention: 512 threads, 16 warps = (m 0-7) x (jhalf 0-1),
// 128 q-rows/block, K'=128, packed fast exp, final cross-warp O reduction
// ============================================================================
#define AQE_H  0
#define AQE_L  34816
#define AKH    69632
#define AKL    87040
#define AVH    104448
#define AVL    117760
#define ASRX   69632            // [128][34] fp32, phase-1 overlay of K' region
#define AOBUF  0                // [128][96] fp32, end overlay of QE region
#define ASSUM  49152            // [128] fp32
#define ATTN_SMEM2 138240

__global__ void __launch_bounds__(512) attn_fa2_kernel(
    const float* __restrict__ rph, const float* __restrict__ rpw,
    const float* __restrict__ rpt)
{
    extern __shared__ char sm[];
    float* srx = (float*)(sm + ASRX);
    __nv_bfloat16* QEh = (__nv_bfloat16*)(sm + AQE_H);
    __nv_bfloat16* QEl = (__nv_bfloat16*)(sm + AQE_L);
    float* Obuf = (float*)(sm + AOBUF);
    float* ssum1 = (float*)(sm + ASSUM);
    u32 smb = smem_u32(sm);

    int tid = threadIdx.x;
    int warp = tid >> 5, lane = tid & 31;
    int wm = warp & 7, jhalf = warp >> 3;
    int gr = lane >> 2;
    int wr0 = wm * 16;
    int jbase = jhalf * 32;
    int bh = blockIdx.y;
    int q0 = blockIdx.x * 128;
    const float* qp = g_qp + (size_t)bh * QN * 96;
    const __nv_bfloat16* qsh = g_qph + (size_t)bh * QN * 96;
    const __nv_bfloat16* qsl = g_qpl + (size_t)bh * QN * 96;
    const __nv_bfloat16* keh = g_keh + (size_t)bh * KNP * 128;
    const __nv_bfloat16* kel = g_kel + (size_t)bh * KNP * 128;
    const __nv_bfloat16* vph = g_vph + (size_t)bh * KN * 96;
    const __nv_bfloat16* vpl = g_vpl + (size_t)bh * KN * 96;

    // ---- phase 1: stage pre-split Q into QE cols 0..95 ----
    #pragma unroll
    for (int k6 = 0; k6 < 6; ++k6) {
        int l = tid + k6 * 512;          // 128 rows x 12 segs x 2 bufs = 3072
        int buf = l >= 1536;
        int rem = l - buf * 1536;
        int row = rem / 12, seg = rem - row * 12;
        int qr = q0 + row;
        u32 dst = smb + (buf ? AQE_L : AQE_H) + (u32)row * 272u + (u32)seg * 16u;
        cpa16(dst, (buf ? qsl : qsh) + (size_t)qr * 96 + seg * 8, (qr < QN) ? 16 : 0);
    }
    CP_COMMIT();
    CP_WAIT0();
    __syncthreads();

    // ---- rel-pos dots from QE (hi+lo) into srx ----
    for (int idx = tid; idx < 128 * 22; idx += 512) {
        int qi = idx / 22, r = idx - qi * 22;
        int qr = q0 + qi;
        float s = 0.f;
        if (qr > 0 && qr < QN) {
            int tok = qr - 1;
            int tq = tok / (QH * QW);
            int hq = (tok / QW) % QH;
            int wq = tok % QW;
            const float* tab;
            if (r < 8)       tab = rpt + (size_t)(tq - r + 7) * 96;
            else if (r < 15) tab = rph + (size_t)(hq - 4 * (r - 8) + 24) * 96;
            else             tab = rpw + (size_t)(wq - 4 * (r - 15) + 24) * 96;
            const __nv_bfloat162* qh2 = (const __nv_bfloat162*)&QEh[qi * 136];
            const __nv_bfloat162* ql2 = (const __nv_bfloat162*)&QEl[qi * 136];
            u64 acc = 0ull;
            #pragma unroll 8
            for (int k = 0; k < 48; ++k) {
                float2 h = __bfloat1622float2(qh2[k]);
                float2 lo = __bfloat1622float2(ql2[k]);
                u64 qv = pk2(h.x + lo.x, h.y + lo.y);
                acc = fma2o(qv, *(const u64*)&tab[2 * k], acc);
            }
            float2 pr = u2f(acc);
            s = pr.x + pr.y;
        }
        srx[qi * 34 + r] = s;
    }
    __syncthreads();

    // ---- fill QE ext cols 96..127 (srel, -50 mask, zeros) ----
    for (int l = tid; l < 128 * 16; l += 512) {
        int row = l >> 4, cp = l & 15;
        int col = 96 + 2 * cp;
        int r0c = 2 * cp, r1c = r0c + 1;
        float2 v;
        v.x = (r0c < 22) ? srx[row * 34 + r0c] : ((r0c == 22) ? -50.f : 0.f);
        v.y = (r1c < 22) ? srx[row * 34 + r1c] : ((r1c == 22) ? -50.f : 0.f);
        split_store(QEh, QEl, (size_t)row * 136 + col, v);
    }
    __syncthreads();   // QE built; srx dead -> K'/V region free

    int qrA = q0 + wr0 + gr;
    int qrB = qrA + 8;

    float O[12][4];
    #pragma unroll
    for (int nt = 0; nt < 12; ++nt)
        #pragma unroll
        for (int i = 0; i < 4; ++i) O[nt][i] = 0.f;
    u64 sumA2 = 0ull, sumB2 = 0ull;

    for (int ch = 0; ch < 7; ++ch) {
        int j0 = ch * 64;
        // stage K' (64 x 272B x2) and V (64 x 208B x2)
        #pragma unroll
        for (int k4 = 0; k4 < 4; ++k4) {
            int l = tid + k4 * 512;      // 2048
            int buf = l >> 10, rem = l & 1023;
            int row = rem >> 4, seg = rem & 15;
            u32 dst = smb + AKH + (u32)buf * 17408u + (u32)row * 272u + (u32)seg * 16u;
            cpa16(dst, (buf ? kel : keh) + ((size_t)(j0 + row)) * 128 + seg * 8, 16);
        }
        #pragma unroll
        for (int k3 = 0; k3 < 3; ++k3) {
            int l = tid + k3 * 512;      // 1536
            int buf = l / 768, rem = l - buf * 768;
            int row = rem / 12, seg = rem - row * 12;
            int j = j0 + row;
            u32 dst = smb + AVH + (u32)buf * 13312u + (u32)row * 208u + (u32)seg * 16u;
            cpa16(dst, (buf ? vpl : vph) + (size_t)j * 96 + seg * 8, (j < KN) ? 16 : 0);
        }
        CP_COMMIT();
        CP_WAIT0();
        __syncthreads();

        // ---- Q'K'^T -> finished scores: warp does 16 rows x 32 keys ----
        float S[4][4];
        #pragma unroll
        for (int jt = 0; jt < 4; ++jt)
            #pragma unroll
            for (int i = 0; i < 4; ++i) S[jt][i] = 0.f;

        #pragma unroll
        for (int ks = 0; ks < 8; ++ks) {
            u32 ah4[4], al4[4];
            u32 aaddr = smb + AQE_H + (u32)(wr0 + (lane & 15)) * 272u
                      + (u32)(ks * 16 + ((lane >> 4) << 3)) * 2u;
            ldm_x4(ah4, aaddr);
            ldm_x4(al4, aaddr + (AQE_L - AQE_H));
            #pragma unroll
            for (int jt2 = 0; jt2 < 2; ++jt2) {
                u32 addr = smb + AKH
                         + (u32)(jbase + jt2 * 16 + ((lane >> 4) << 3) + (lane & 7)) * 272u
                         + (u32)(ks * 16 + ((lane >> 3) & 1) * 8) * 2u;
                u32 bh4[4], bl4[4];
                ldm_x4(bh4, addr);
                ldm_x4(bl4, addr + (AKL - AKH));
                mma_bf16(S[2 * jt2],     ah4, bh4);
                mma_bf16(S[2 * jt2],     ah4, bl4);
                mma_bf16(S[2 * jt2],     al4, bh4);
                mma_bf16(S[2 * jt2 + 1], ah4, bh4 + 2);
                mma_bf16(S[2 * jt2 + 1], ah4, bl4 + 2);
                mma_bf16(S[2 * jt2 + 1], al4, bh4 + 2);
            }
        }

        // ---- packed fast exp (padded keys self-mask via -50) ----
        #pragma unroll
        for (int jt = 0; jt < 4; ++jt) {
            u64 eA = fexp2(S[jt][0], S[jt][1]);
            u64 eB = fexp2(S[jt][2], S[jt][3]);
            sumA2 = add2(sumA2, eA);
            sumB2 = add2(sumB2, eB);
            float2 fa = u2f(eA), fb = u2f(eB);
            S[jt][0] = fa.x; S[jt][1] = fa.y;
            S[jt][2] = fb.x; S[jt][3] = fb.y;
        }

        // ---- repack S as P a-fragments (hi/lo) ----
        u32 ph[2][4], pl[2][4];
        #pragma unroll
        for (int t = 0; t < 2; ++t) {
            ph[t][0] = pack_hi(S[2 * t][0],     S[2 * t][1],     pl[t][0]);
            ph[t][1] = pack_hi(S[2 * t][2],     S[2 * t][3],     pl[t][1]);
            ph[t][2] = pack_hi(S[2 * t + 1][0], S[2 * t + 1][1], pl[t][2]);
            ph[t][3] = pack_hi(S[2 * t + 1][2], S[2 * t + 1][3], pl[t][3]);
        }

        // ---- P @ V over this warp's 32 keys ----
        #pragma unroll
        for (int kt = 0; kt < 2; ++kt) {
            #pragma unroll
            for (int nt2 = 0; nt2 < 6; ++nt2) {
                u32 addr = smb + AVH
                         + (u32)(jbase + kt * 16 + ((lane >> 3) & 1) * 8 + (lane & 7)) * 208u
                         + (u32)(nt2 * 16 + ((lane >> 4) << 3)) * 2u;
                u32 vh4[4], vl4[4];
                ldm_x4t(vh4, addr);
                ldm_x4t(vl4, addr + (AVL - AVH));
                mma_bf16(O[2 * nt2],     ph[kt], vh4);
                mma_bf16(O[2 * nt2],     ph[kt], vl4);
                mma_bf16(O[2 * nt2],     pl[kt], vh4);
                mma_bf16(O[2 * nt2 + 1], ph[kt], vh4 + 2);
                mma_bf16(O[2 * nt2 + 1], ph[kt], vl4 + 2);
                mma_bf16(O[2 * nt2 + 1], pl[kt], vh4 + 2);
            }
        }
        __syncthreads();
    }

    // ---- sums: horizontal + quad reduce ----
    float2 sa = u2f(sumA2), sb = u2f(sumB2);
    float sumA = sa.x + sa.y;
    float sumB = sb.x + sb.y;
    sumA += __shfl_xor_sync(0xffffffffu, sumA, 1);
    sumA += __shfl_xor_sync(0xffffffffu, sumA, 2);
    sumB += __shfl_xor_sync(0xffffffffu, sumB, 1);
    sumB += __shfl_xor_sync(0xffffffffu, sumB, 2);

    // ---- cross-warp (jhalf) O + sum reduction via smem (QE region dead) ----
    int gc = 2 * (lane & 3);
    if (jhalf == 1) {
        #pragma unroll
        for (int nt = 0; nt < 12; ++nt) {
            int col = nt * 8 + gc;
            *(float2*)&Obuf[(wr0 + gr) * 96 + col]     = make_float2(O[nt][0], O[nt][1]);
            *(float2*)&Obuf[(wr0 + 8 + gr) * 96 + col] = make_float2(O[nt][2], O[nt][3]);
        }
        if ((lane & 3) == 0) {
            ssum1[wr0 + gr] = sumA;
            ssum1[wr0 + 8 + gr] = sumB;
        }
    }
    __syncthreads();
    if (jhalf == 0) {
        sumA += ssum1[wr0 + gr];
        sumB += ssum1[wr0 + 8 + gr];
        float riA = 1.f / sumA;
        float riB = 1.f / sumB;
        int b = bh >> 1, head = bh & 1;
        #pragma unroll
        for (int nt = 0; nt < 12; ++nt) {
            int col = nt * 8 + gc;
            float2 oA = *(const float2*)&Obuf[(wr0 + gr) * 96 + col];
            float2 oB = *(const float2*)&Obuf[(wr0 + 8 + gr) * 96 + col];
            if (qrA < QN) {
                float2 qv = *(const float2*)&qp[(size_t)qrA * 96 + col];
                float2 o = make_float2((O[nt][0] + oA.x) * riA + qv.x,
                                       (O[nt][1] + oA.y) * riA + qv.y);
                split_store(g_aoh, g_aol,
                            ((size_t)(b * QN + qrA)) * 192 + head * 96 + col, o);
            }
            if (qrB < QN) {
                float2 qv = *(const float2*)&qp[(size_t)qrB * 96 + col];
                float2 o = make_float2((O[nt][2] + oB.x) * riB + qv.x,
                                       (O[nt][3] + oB.y) * riB + qv.y);
                split_store(g_aoh, g_aol,
                            ((size_t)(b * QN + qrB)) * 192 + head * 96 + col, o);
            }
        }
    }
}

// ---------------- launch ----------------
extern "C" void kernel_launch(void* const* d_in, const int* in_sizes, int n_in,
                              void* d_out, int out_size)
{
    const float* x      = (const float*)d_in[0];
    const float* qkv_w  = (const float*)d_in[1];
    const float* qkv_b  = (const float*)d_in[2];
    const float* proj_w = (const float*)d_in[3];
    const float* proj_b = (const float*)d_in[4];
    const float* pq_w   = (const float*)d_in[5];
    const float* nq_g   = (const float*)d_in[6];
    const float* nq_b   = (const float*)d_in[7];
    const float* pk_w   = (const float*)d_in[8];
    const float* nk_g   = (const float*)d_in[9];
    const float* nk_b   = (const float*)d_in[10];
    const float* pv_w   = (const float*)d_in[11];
    const float* nv_g   = (const float*)d_in[12];
    const float* nv_b   = (const float*)d_in[13];
    const float* rph    = (const float*)d_in[14];
    const float* rpw    = (const float*)d_in[15];
    const float* rpt    = (const float*)d_in[16];

    int B = in_sizes[0] / (N_IN * 96);
    if (B > B_MAX) B = B_MAX;
    int M   = B * N_IN;
    int Mkv = B * NKV;
    int nbQ  = (M + 127) / 128;
    int nbKV = (Mkv + 127) / 128;

    cudaFuncSetAttribute(gemm_bf16, cudaFuncAttributeMaxDynamicSharedMemorySize, GEMM_SMEM);
    cudaFuncSetAttribute(attn_fa2_kernel, cudaFuncAttributeMaxDynamicSharedMemorySize, ATTN_SMEM2);

    int nx = M * 48;
    int totalPairs = nx + 576 * 96 / 2 + 192 * 192 / 2;
    presplit_kernel<<<(totalPairs + 255) / 256, 256>>>(x, qkv_w, proj_w, nx);

    gemm_bf16<<<nbQ + 2 * nbKV, 256, GEMM_SMEM>>>(qkv_b, nullptr, M, Mkv, 96, nbQ, nbKV, 1);

    int nSpatial = B * 2 * QH * QW;
    int nPQ  = nSpatial + B * 2;
    int nPKV = B * 2 * KNP;
    pool_all_kernel<<<nPQ + 2 * nPKV, 96>>>(pq_w, nq_g, nq_b, pk_w, nk_g, nk_b,
                                            pv_w, nv_g, nv_b, nSpatial, nPQ, nPKV);
    attn_fa2_kernel<<<dim3((QN + 127) / 128, B * 2), 512, ATTN_SMEM2>>>(rph, rpw, rpt);

    gemm_bf16<<<(B * QN + 127) / 128, 256, GEMM_SMEM>>>(proj_b, (float*)d_out,
                                                        B * QN, 0, 192, 0, 0, 0);
}

// round 16
// speedup vs baseline: 1.0274x; 1.0274x over previous
#include <cuda_runtime.h>
#include <cuda_bf16.h>
#include <math.h>

typedef unsigned long long u64;
typedef unsigned int u32;

#define B_MAX 4
#define N_IN 25089      // 1 + 8*56*56
#define T_IN 8
#define H_IN 56
#define W_IN 56
#define QT 8
#define QH 28
#define QW 28
#define QN 6273         // 1 + 8*28*28
#define KT 8
#define KH 7
#define KW 7
#define KN 393          // 1 + 8*7*7
#define KNP 448         // padded key count
#define NKV 3201        // 1 + 8*20*20 gathered tokens per batch
#define ATTN_SCALE 0.102062072615965745f   // 1/sqrt(96)

// ---------------- scratch (device globals; no allocation) ----------------
__device__ float g_q [(size_t)B_MAX * N_IN * 192];
__device__ float g_k [(size_t)B_MAX * NKV * 192];
__device__ float g_v [(size_t)B_MAX * NKV * 192];
__device__ float g_qp[(size_t)B_MAX * 2 * QN * 96];
// bf16 hi/lo pre-split tensors
__device__ __nv_bfloat16 g_xh[(size_t)B_MAX * N_IN * 96];
__device__ __nv_bfloat16 g_xl[(size_t)B_MAX * N_IN * 96];
__device__ __nv_bfloat16 g_wh[576 * 96];
__device__ __nv_bfloat16 g_wl[576 * 96];
__device__ __nv_bfloat16 g_pwh[192 * 192];
__device__ __nv_bfloat16 g_pwl[192 * 192];
__device__ __nv_bfloat16 g_aoh[(size_t)B_MAX * QN * 192];
__device__ __nv_bfloat16 g_aol[(size_t)B_MAX * QN * 192];
// pooled q pre-split (unscaled)
__device__ __nv_bfloat16 g_qph[(size_t)B_MAX * 2 * QN * 96];
__device__ __nv_bfloat16 g_qpl[(size_t)B_MAX * 2 * QN * 96];
// extended pooled K (128 cols: 96 scaled ch + 22 onehot + mask + pad) and pooled V
__device__ __nv_bfloat16 g_keh[(size_t)B_MAX * 2 * KNP * 128];
__device__ __nv_bfloat16 g_kel[(size_t)B_MAX * 2 * KNP * 128];
__device__ __nv_bfloat16 g_vph[(size_t)B_MAX * 2 * KN * 96];
__device__ __nv_bfloat16 g_vpl[(size_t)B_MAX * 2 * KN * 96];

// ---------------- helpers ----------------
__device__ __forceinline__ int hw_from_idx(int i) {
    return (i < 2) ? i : 7 + ((i - 2) / 3) * 8 + ((i - 2) % 3);
}
__device__ __forceinline__ u32 smem_u32(const void* p) {
    u32 a;
    asm("{ .reg .u64 t; cvta.to.shared.u64 t, %1; cvt.u32.u64 %0, t; }" : "=r"(a) : "l"(p));
    return a;
}
__device__ __forceinline__ u64 fma2o(u64 a, u64 b, u64 c) {
    u64 d; asm("fma.rn.f32x2 %0, %1, %2, %3;" : "=l"(d) : "l"(a), "l"(b), "l"(c)); return d;
}
__device__ __forceinline__ u64 add2(u64 a, u64 b) {
    u64 d; asm("add.rn.f32x2 %0, %1, %2;" : "=l"(d) : "l"(a), "l"(b)); return d;
}
__device__ __forceinline__ u64 mul2(u64 a, u64 b) {
    u64 d; asm("mul.rn.f32x2 %0, %1, %2;" : "=l"(d) : "l"(a), "l"(b)); return d;
}
__device__ __forceinline__ u64 dupf(float v) {
    u64 r; asm("mov.b64 %0, {%1, %1};" : "=l"(r) : "f"(v)); return r;
}
__device__ __forceinline__ float2 u2f(u64 v) {
    float2 r; asm("mov.b64 {%0, %1}, %2;" : "=f"(r.x), "=f"(r.y) : "l"(v)); return r;
}
__device__ __forceinline__ u64 pk2(float a, float b) {
    u64 r; asm("mov.b64 %0, {%1, %2};" : "=l"(r) : "f"(a), "f"(b)); return r;
}
// packed fast exp: e^x for two lanes, poly deg-4, rel err ~4e-5
__device__ __forceinline__ u64 fexp2(float a, float b) {
    u64 x2 = pk2(a, b);
    u64 t2 = fma2o(x2, dupf(1.4426950408889634f), dupf(12582912.f));
    u64 n2 = add2(t2, dupf(-12582912.f));
    u64 r2 = fma2o(n2, dupf(-0.6931471805599453f), x2);
    u64 p2 = fma2o(r2, dupf(4.1666667e-2f), dupf(1.6666667e-1f));
    p2 = fma2o(p2, r2, dupf(0.5f));
    p2 = fma2o(p2, r2, dupf(1.0f));
    p2 = fma2o(p2, r2, dupf(1.0f));
    u32 tl = (u32)t2, th = (u32)(t2 >> 32);
    u32 sl = (tl << 23) + 0x3f800000u;
    u32 sh = (th << 23) + 0x3f800000u;
    u64 s2 = ((u64)sh << 32) | (u64)sl;
    return mul2(p2, s2);
}

// ---------------- mma.sync helpers ----------------
__device__ __forceinline__ void ldm_x4(u32* r, u32 addr) {
    asm volatile("ldmatrix.sync.aligned.m8n8.x4.shared.b16 {%0,%1,%2,%3}, [%4];"
        : "=r"(r[0]), "=r"(r[1]), "=r"(r[2]), "=r"(r[3]) : "r"(addr));
}
__device__ __forceinline__ void ldm_x4t(u32* r, u32 addr) {
    asm volatile("ldmatrix.sync.aligned.m8n8.x4.trans.shared.b16 {%0,%1,%2,%3}, [%4];"
        : "=r"(r[0]), "=r"(r[1]), "=r"(r[2]), "=r"(r[3]) : "r"(addr));
}
__device__ __forceinline__ void mma_bf16(float* c, const u32* a, const u32* b) {
    asm volatile("mma.sync.aligned.m16n8k16.row.col.f32.bf16.bf16.f32 "
        "{%0,%1,%2,%3}, {%4,%5,%6,%7}, {%8,%9}, {%0,%1,%2,%3};"
        : "+f"(c[0]), "+f"(c[1]), "+f"(c[2]), "+f"(c[3])
        : "r"(a[0]), "r"(a[1]), "r"(a[2]), "r"(a[3]), "r"(b[0]), "r"(b[1]));
}
__device__ __forceinline__ void split_store(__nv_bfloat16* hi, __nv_bfloat16* lo,
                                            size_t idx, float2 v) {
    __nv_bfloat162 h = __floats2bfloat162_rn(v.x, v.y);
    __nv_bfloat162 l = __floats2bfloat162_rn(v.x - __bfloat162float(h.x),
                                             v.y - __bfloat162float(h.y));
    *(__nv_bfloat162*)(hi + idx) = h;
    *(__nv_bfloat162*)(lo + idx) = l;
}
__device__ __forceinline__ u32 pack_hi(float a, float b, u32& lo) {
    __nv_bfloat162 h = __floats2bfloat162_rn(a, b);
    __nv_bfloat162 l = __floats2bfloat162_rn(a - __bfloat162float(h.x),
                                             b - __bfloat162float(h.y));
    lo = *(u32*)&l;
    return *(u32*)&h;
}
__device__ __forceinline__ void cpa16(u32 dst, const void* src, int srcsize) {
    asm volatile("cp.async.cg.shared.global [%0], [%1], 16, %2;"
        :: "r"(dst), "l"(src), "r"(srcsize));
}
#define CP_COMMIT() asm volatile("cp.async.commit_group;" ::: "memory")
#define CP_WAIT0()  asm volatile("cp.async.wait_group 0;" ::: "memory")
#define CP_WAIT1()  asm volatile("cp.async.wait_group 1;" ::: "memory")

// ---------------- presplit: x / qkv_w / proj_w -> bf16 hi/lo ----------------
__global__ void presplit_kernel(const float* __restrict__ x,
                                const float* __restrict__ qkv_w,
                                const float* __restrict__ proj_w, int nx)
{
    int i = blockIdx.x * 256 + threadIdx.x;
    const int nqkv = 576 * 96 / 2;
    const int nproj = 192 * 192 / 2;
    const float* src;
    __nv_bfloat16 *dh, *dl;
    int off;
    if (i < nx)                   { src = x;      dh = g_xh;  dl = g_xl;  off = i; }
    else if (i < nx + nqkv)       { src = qkv_w;  dh = g_wh;  dl = g_wl;  off = i - nx; }
    else if (i < nx + nqkv + nproj) { src = proj_w; dh = g_pwh; dl = g_pwl; off = i - nx - nqkv; }
    else return;
    float2 v = ((const float2*)src)[off];
    split_store(dh, dl, (size_t)(2 * off), v);
}

// ============================================================================
// cp.async double-buffered bf16 tensor-core GEMM (unchanged)
// ============================================================================
#define STG_BYTES 51200
#define STG_AL 10240
#define STG_B  20480
#define STG_BL 15360
#define GEMM_SMEM (2 * STG_BYTES)

__global__ void __launch_bounds__(256) gemm_bf16(
    const float* __restrict__ bias_all, float* __restrict__ outp,
    int Mq, int Mkv, int K, int nbQ, int nbKV, int fused)
{
    extern __shared__ char sm[];
    u32 smb = smem_u32(sm);

    int tid = threadIdx.x;
    int warp = tid >> 5, lane = tid & 31;
    int rm = (warp & 3) * 32;
    int cn = (warp >> 2) * 96;

    const __nv_bfloat16 *Asrc_h, *Asrc_l, *Bsrc_h, *Bsrc_l;
    const float* bp;
    float* out;
    int r0, Mloc;
    bool gather = false;
    if (!fused) {
        Asrc_h = g_aoh; Asrc_l = g_aol; Bsrc_h = g_pwh; Bsrc_l = g_pwl;
        bp = bias_all; out = outp; r0 = blockIdx.x * 128; Mloc = Mq;
    } else if ((int)blockIdx.x < nbQ) {
        Asrc_h = g_xh; Asrc_l = g_xl; Bsrc_h = g_wh; Bsrc_l = g_wl;
        bp = bias_all; out = (float*)g_q; r0 = blockIdx.x * 128; Mloc = Mq;
    } else {
        int t = blockIdx.x - nbQ;
        int sel = t / nbKV, bx2 = t - sel * nbKV;
        gather = true;
        Asrc_h = g_xh; Asrc_l = g_xl;
        Bsrc_h = g_wh + (size_t)(1 + sel) * 192 * 96;
        Bsrc_l = g_wl + (size_t)(1 + sel) * 192 * 96;
        bp = bias_all + (1 + sel) * 192;
        out = sel ? (float*)g_v : (float*)g_k;
        r0 = bx2 * 128; Mloc = Mkv;
    }

    size_t aoff[4];
    int asz[4];
    #pragma unroll
    for (int k4 = 0; k4 < 4; ++k4) {
        int l = tid + k4 * 256;
        int row = l >> 3;
        int r = r0 + row;
        if (r < Mloc) {
            asz[k4] = 16;
            if (gather) {
                int b = r / NKV, ci = r - b * NKV;
                int n = 0;
                if (ci > 0) {
                    int cc = ci - 1;
                    int it = cc / 400, rem = cc - it * 400;
                    int h = hw_from_idx(rem / 20), wv = hw_from_idx(rem % 20);
                    n = 1 + (it * H_IN + h) * W_IN + wv;
                }
                aoff[k4] = ((size_t)b * N_IN + n) * 96;
            } else {
                aoff[k4] = (size_t)r * K;
            }
        } else { aoff[k4] = 0; asz[k4] = 0; }
    }

    float C[2][12][4];
    #pragma unroll
    for (int mt = 0; mt < 2; ++mt)
        #pragma unroll
        for (int nt = 0; nt < 12; ++nt)
            #pragma unroll
            for (int i = 0; i < 4; ++i) C[mt][nt][i] = 0.f;

    int nch = K / 32;

    #define ISSUE_CHUNK(c_, st_) do {                                          \
        int kc = (c_) * 32;                                                    \
        u32 sb = smb + (st_) * STG_BYTES;                                      \
        _Pragma("unroll")                                                      \
        for (int k4 = 0; k4 < 4; ++k4) {                                       \
            int l = tid + k4 * 256;                                            \
            int row = l >> 3, hl = (l >> 2) & 1, seg = l & 3;                  \
            u32 dst = sb + hl * STG_AL + (u32)row * 80u + (u32)seg * 16u;      \
            const __nv_bfloat16* s0 = hl ? Asrc_l : Asrc_h;                    \
            cpa16(dst, s0 + aoff[k4] + kc + seg * 8, asz[k4]);                 \
        }                                                                      \
        _Pragma("unroll")                                                      \
        for (int k6 = 0; k6 < 6; ++k6) {                                       \
            int l = tid + k6 * 256;                                            \
            int row = l >> 3, hl = (l >> 2) & 1, seg = l & 3;                  \
            u32 dst = sb + STG_B + hl * STG_BL + (u32)row * 80u + (u32)seg * 16u; \
            const __nv_bfloat16* s0 = hl ? Bsrc_l : Bsrc_h;                    \
            cpa16(dst, s0 + (size_t)row * K + kc + seg * 8, 16);               \
        }                                                                      \
        CP_COMMIT();                                                           \
    } while (0)

    ISSUE_CHUNK(0, 0);

    for (int c = 0; c < nch; ++c) {
        int st = c & 1;
        if (c + 1 < nch) {
            ISSUE_CHUNK(c + 1, st ^ 1);
            CP_WAIT1();
        } else {
            CP_WAIT0();
        }
        __syncthreads();

        u32 sb = smb + st * STG_BYTES;
        #pragma unroll
        for (int ks = 0; ks < 2; ++ks) {
            int k0 = ks * 16;
            u32 ah[2][4], al[2][4];
            #pragma unroll
            for (int mt = 0; mt < 2; ++mt) {
                u32 off = (u32)(rm + mt * 16 + (lane & 15)) * 80u
                        + (u32)(k0 + ((lane >> 4) << 3)) * 2u;
                ldm_x4(ah[mt], sb + off);
                ldm_x4(al[mt], sb + STG_AL + off);
            }
            #pragma unroll
            for (int np = 0; np < 6; ++np) {
                u32 off = (u32)(cn + np * 16 + ((lane >> 4) << 3) + (lane & 7)) * 80u
                        + (u32)(k0 + (((lane >> 3) & 1) << 3)) * 2u;
                u32 bh4[4], bl4[4];
                ldm_x4(bh4, sb + STG_B + off);
                ldm_x4(bl4, sb + STG_B + STG_BL + off);
                #pragma unroll
                for (int mt = 0; mt < 2; ++mt) {
                    mma_bf16(C[mt][2 * np],     ah[mt], bh4);
                    mma_bf16(C[mt][2 * np],     ah[mt], bl4);
                    mma_bf16(C[mt][2 * np],     al[mt], bh4);
                    mma_bf16(C[mt][2 * np + 1], ah[mt], bh4 + 2);
                    mma_bf16(C[mt][2 * np + 1], ah[mt], bl4 + 2);
                    mma_bf16(C[mt][2 * np + 1], al[mt], bh4 + 2);
                }
            }
        }
        __syncthreads();
    }

    int gr = lane >> 2;
    int gc = (lane & 3) * 2;
    #pragma unroll
    for (int mt = 0; mt < 2; ++mt) {
        int row0 = r0 + rm + mt * 16 + gr;
        int row1 = row0 + 8;
        #pragma unroll
        for (int nt = 0; nt < 12; ++nt) {
            int col = cn + nt * 8 + gc;
            float b0 = bp[col], b1 = bp[col + 1];
            if (row0 < Mloc) {
                float2 o = make_float2(C[mt][nt][0] + b0, C[mt][nt][1] + b1);
                *(float2*)&out[(size_t)row0 * 192 + col] = o;
            }
            if (row1 < Mloc) {
                float2 o = make_float2(C[mt][nt][2] + b0, C[mt][nt][3] + b1);
                *(float2*)&out[(size_t)row1 * 192 + col] = o;
            }
        }
    }
}

// ---------------- LN helper (96 threads) ----------------
__device__ __forceinline__ float ln96(float val, const float* gg, const float* bb, int c,
                                      float* p1, float* p2, float* mv)
{
    float s1 = val, s2 = val * val;
    #pragma unroll
    for (int off = 16; off > 0; off >>= 1) {
        s1 += __shfl_xor_sync(0xffffffffu, s1, off);
        s2 += __shfl_xor_sync(0xffffffffu, s2, off);
    }
    int wid = c >> 5, lane = c & 31;
    if (lane == 0) { p1[wid] = s1; p2[wid] = s2; }
    __syncthreads();
    if (c == 0) {
        float t1 = p1[0] + p1[1] + p1[2];
        float t2 = p2[0] + p2[1] + p2[2];
        float mean = t1 / 96.f;
        float var  = t2 / 96.f - mean * mean;
        mv[0] = mean; mv[1] = rsqrtf(var + 1e-5f);
    }
    __syncthreads();
    return (val - mv[0]) * mv[1] * gg[c] + bb[c];
}

// ---------------- merged pool kernel ----------------
__global__ void pool_all_kernel(
    const float* __restrict__ cwq, const float* __restrict__ ggq, const float* __restrict__ bbq,
    const float* __restrict__ cwk, const float* __restrict__ ggk, const float* __restrict__ bbk,
    const float* __restrict__ cwv, const float* __restrict__ ggv, const float* __restrict__ bbv,
    int nSpatial, int nPQ, int nPKV)
{
    __shared__ float p1[3], p2[3], mv[2];
    int bx = blockIdx.x;
    int c = threadIdx.x;

    if (bx < nPQ) {
        int o = bx;
        if (o >= nSpatial) {
            int idx = o - nSpatial;
            int head = idx & 1, b = idx >> 1;
            float val = g_q[((size_t)b * N_IN) * 192 + head * 96 + c];
            float outv = ln96(val, ggq, bbq, c, p1, p2, mv);
            size_t oi = ((size_t)((b * 2 + head) * QN)) * 96 + c;
            g_qp[oi] = outv;
            __nv_bfloat16 h = __float2bfloat16(outv);
            g_qph[oi] = h;
            g_qpl[oi] = __float2bfloat16(outv - __bfloat162float(h));
            return;
        }
        int w2 = o % QW;
        int h2 = (o / QW) % QH;
        int head = (o / (QW * QH)) & 1;
        int b = o / (QW * QH * 2);

        float wreg[27];
        #pragma unroll
        for (int t = 0; t < 27; ++t) wreg[t] = cwq[c * 27 + t];

        float ps[8][3];
        #pragma unroll
        for (int it = 0; it < 8; ++it)
            #pragma unroll
            for (int d = 0; d < 3; ++d) ps[it][d] = 0.f;

        const float* base = g_q + ((size_t)(b * N_IN + 1)) * 192 + head * 96 + c;
        #pragma unroll
        for (int dh = 0; dh < 3; ++dh) {
            int ih = 2 * h2 - 1 + dh;
            if (ih < 0 || ih >= H_IN) continue;
            #pragma unroll
            for (int dw = 0; dw < 3; ++dw) {
                int iw = 2 * w2 - 1 + dw;
                if (iw < 0 || iw >= W_IN) continue;
                float w0 = wreg[(0 * 3 + dh) * 3 + dw];
                float w1 = wreg[(1 * 3 + dh) * 3 + dw];
                float w2r = wreg[(2 * 3 + dh) * 3 + dw];
                #pragma unroll
                for (int it = 0; it < 8; ++it) {
                    int tok = (it * H_IN + ih) * W_IN + iw;
                    float v = base[(size_t)tok * 192];
                    ps[it][0] = fmaf(w0, v, ps[it][0]);
                    ps[it][1] = fmaf(w1, v, ps[it][1]);
                    ps[it][2] = fmaf(w2r, v, ps[it][2]);
                }
            }
        }
        for (int t2 = 0; t2 < QT; ++t2) {
            float s = ps[t2][1];
            if (t2 > 0) s += ps[t2 - 1][0];
            if (t2 < 7) s += ps[t2 + 1][2];
            float outv = ln96(s, ggq, bbq, c, p1, p2, mv);
            int n = 1 + (t2 * QH + h2) * QW + w2;
            size_t oi = ((size_t)((b * 2 + head) * QN) + n) * 96 + c;
            g_qp[oi] = outv;
            __nv_bfloat16 h = __float2bfloat16(outv);
            g_qph[oi] = h;
            g_qpl[oi] = __float2bfloat16(outv - __bfloat162float(h));
            __syncthreads();
        }
        return;
    }

    int t = bx - nPQ;
    int whichV = t / nPKV;
    int o = t - whichV * nPKV;
    const float* cw = whichV ? cwv : cwk;
    const float* gg = whichV ? ggv : ggk;
    const float* bb = whichV ? bbv : bbk;
    int n    = o % KNP;
    int head = (o / KNP) & 1;
    int b    = o / (KNP * 2);
    int bh   = b * 2 + head;

    if (n >= KN) {
        if (whichV) return;
        size_t rb = ((size_t)bh * KNP + n) * 128;
        __nv_bfloat16 z = __float2bfloat16(0.f);
        g_keh[rb + c] = z; g_kel[rb + c] = z;
        if (c < 32) {
            g_keh[rb + 96 + c] = __float2bfloat16((c == 22) ? 1.f : 0.f);
            g_kel[rb + 96 + c] = z;
        }
        return;
    }

    const float* src = whichV ? g_v : g_k;
    float val;
    if (n == 0) {
        val = src[((size_t)b * NKV) * 192 + head * 96 + c];
    } else {
        int tn  = n - 1;
        int t2  = tn / (KH * KW);
        int rem = tn % (KH * KW);
        int h2  = rem / KW, w2 = rem % KW;
        float s = 0.f;
        #pragma unroll
        for (int dt = 0; dt < 3; ++dt) {
            int it = t2 + dt - 1;
            if (it < 0 || it >= T_IN) continue;
            #pragma unroll
            for (int dh = 0; dh < 3; ++dh) {
                int ih = h2 * 8 + dh - 1;
                if (ih < 0 || ih >= H_IN) continue;
                #pragma unroll
                for (int dw = 0; dw < 3; ++dw) {
                    int iw = w2 * 8 + dw - 1;
                    if (iw < 0 || iw >= W_IN) continue;
                    int hi2 = (ih <= 1) ? ih : 2 + ((ih - 7) >> 3) * 3 + ((ih - 7) & 7);
                    int wi2 = (iw <= 1) ? iw : 2 + ((iw - 7) >> 3) * 3 + ((iw - 7) & 7);
                    int ci = 1 + (it * 20 + hi2) * 20 + wi2;
                    s = fmaf(cw[c * 27 + (dt * 3 + dh) * 3 + dw],
                             src[((size_t)(b * NKV + ci)) * 192 + head * 96 + c], s);
                }
            }
        }
        val = s;
    }
    float outv = ln96(val, gg, bb, c, p1, p2, mv);
    if (whichV) {
        size_t oidx = ((size_t)bh * KN + n) * 96 + c;
        __nv_bfloat16 h = __float2bfloat16(outv);
        g_vph[oidx] = h;
        g_vpl[oidx] = __float2bfloat16(outv - __bfloat162float(h));
    } else {
        // fold ATTN_SCALE into K channels
        float sv = outv * ATTN_SCALE;
        size_t rb = ((size_t)bh * KNP + n) * 128;
        __nv_bfloat16 h = __float2bfloat16(sv);
        g_keh[rb + c] = h;
        g_kel[rb + c] = __float2bfloat16(sv - __bfloat162float(h));
        if (c < 32) {
            float ev = 0.f;
            if (n > 0 && c < 22) {
                int kk = n - 1, kt = kk / 49, rm = kk % 49;
                int rh = rm / 7, rw = rm % 7;
                if (c == kt || c == 8 + rh || c == 15 + rw) ev = 1.f;
            }
            g_keh[rb + 96 + c] = __float2bfloat16(ev);
            g_kel[rb + 96 + c] = __float2bfloat16(0.f);
        }
    }
}

// ============================================================================
// FA2 attention: 256 threads, 8 warps = (m 0-3) x (jhalf 0-1),
// 64 q-rows/block, K'=128, packed fast exp, 2 blocks/SM co-resident
// ============================================================================
#define AROWS  64
#define AQE_H  0
#define AQE_L  17408
#define AKH    34816
#define AKL    52224
#define AVH    69632
#define AVL    82944
#define ASRX   69632            // [64][34] fp32, phase-1 overlay of V region
#define AOBUF  0                // [64][96] fp32, end overlay of QE region
#define ASSUM  24576            // [64] fp32
#define ATTN_SMEM2 96256

__global__ void __launch_bounds__(256) attn_fa2_kernel(
    const float* __restrict__ rph, const float* __restrict__ rpw,
    const float* __restrict__ rpt)
{
    extern __shared__ char sm[];
    float* srx = (float*)(sm + ASRX);
    __nv_bfloat16* QEh = (__nv_bfloat16*)(sm + AQE_H);
    __nv_bfloat16* QEl = (__nv_bfloat16*)(sm + AQE_L);
    float* Obuf = (float*)(sm + AOBUF);
    float* ssum1 = (float*)(sm + ASSUM);
    u32 smb = smem_u32(sm);

    int tid = threadIdx.x;
    int warp = tid >> 5, lane = tid & 31;
    int wm = warp & 3, jhalf = warp >> 2;
    int gr = lane >> 2;
    int wr0 = wm * 16;
    int jbase = jhalf * 32;
    int bh = blockIdx.y;
    int q0 = blockIdx.x * AROWS;
    const float* qp = g_qp + (size_t)bh * QN * 96;
    const __nv_bfloat16* qsh = g_qph + (size_t)bh * QN * 96;
    const __nv_bfloat16* qsl = g_qpl + (size_t)bh * QN * 96;
    const __nv_bfloat16* keh = g_keh + (size_t)bh * KNP * 128;
    const __nv_bfloat16* kel = g_kel + (size_t)bh * KNP * 128;
    const __nv_bfloat16* vph = g_vph + (size_t)bh * KN * 96;
    const __nv_bfloat16* vpl = g_vpl + (size_t)bh * KN * 96;

    // ---- phase 1: stage pre-split Q into QE cols 0..95 ----
    #pragma unroll
    for (int k6 = 0; k6 < 6; ++k6) {
        int l = tid + k6 * 256;          // 64 rows x 12 segs x 2 bufs = 1536
        int buf = l >= 768;
        int rem = l - buf * 768;
        int row = rem / 12, seg = rem - row * 12;
        int qr = q0 + row;
        u32 dst = smb + (buf ? AQE_L : AQE_H) + (u32)row * 272u + (u32)seg * 16u;
        cpa16(dst, (buf ? qsl : qsh) + (size_t)qr * 96 + seg * 8, (qr < QN) ? 16 : 0);
    }
    CP_COMMIT();

    // ---- rel-pos dots from fp32 g_qp (global, L1-resident) into srx ----
    for (int idx = tid; idx < AROWS * 22; idx += 256) {
        int qi = idx / 22, r = idx - qi * 22;
        int qr = q0 + qi;
        float s = 0.f;
        if (qr > 0 && qr < QN) {
            int tok = qr - 1;
            int tq = tok / (QH * QW);
            int hq = (tok / QW) % QH;
            int wq = tok % QW;
            const float* tab;
            if (r < 8)       tab = rpt + (size_t)(tq - r + 7) * 96;
            else if (r < 15) tab = rph + (size_t)(hq - 4 * (r - 8) + 24) * 96;
            else             tab = rpw + (size_t)(wq - 4 * (r - 15) + 24) * 96;
            const float* qrow = qp + (size_t)qr * 96;
            u64 acc = 0ull;
            #pragma unroll 8
            for (int k = 0; k < 96; k += 2)
                acc = fma2o(*(const u64*)&qrow[k], *(const u64*)&tab[k], acc);
            float2 pr = u2f(acc);
            s = pr.x + pr.y;
        }
        srx[qi * 34 + r] = s;
    }
    CP_WAIT0();
    __syncthreads();

    // ---- fill QE ext cols 96..127 (srel, -50 mask, zeros) ----
    for (int l = tid; l < AROWS * 16; l += 256) {
        int row = l >> 4, cp = l & 15;
        int col = 96 + 2 * cp;
        int r0c = 2 * cp, r1c = r0c + 1;
        float2 v;
        v.x = (r0c < 22) ? srx[row * 34 + r0c] : ((r0c == 22) ? -50.f : 0.f);
        v.y = (r1c < 22) ? srx[row * 34 + r1c] : ((r1c == 22) ? -50.f : 0.f);
        split_store(QEh, QEl, (size_t)row * 136 + col, v);
    }
    __syncthreads();   // QE built; srx dead -> K'/V regions free

    int qrA = q0 + wr0 + gr;
    int qrB = qrA + 8;

    float O[12][4];
    #pragma unroll
    for (int nt = 0; nt < 12; ++nt)
        #pragma unroll
        for (int i = 0; i < 4; ++i) O[nt][i] = 0.f;
    u64 sumA2 = 0ull, sumB2 = 0ull;

    for (int ch = 0; ch < 7; ++ch) {
        int j0 = ch * 64;
        // stage K' (64 x 272B x2 = 2048 segs) and V (64 x 208B x2 = 1536 segs)
        #pragma unroll
        for (int k8 = 0; k8 < 8; ++k8) {
            int l = tid + k8 * 256;
            int buf = l >> 10, rem = l & 1023;
            int row = rem >> 4, seg = rem & 15;
            u32 dst = smb + AKH + (u32)buf * 17408u + (u32)row * 272u + (u32)seg * 16u;
            cpa16(dst, (buf ? kel : keh) + ((size_t)(j0 + row)) * 128 + seg * 8, 16);
        }
        #pragma unroll
        for (int k6 = 0; k6 < 6; ++k6) {
            int l = tid + k6 * 256;
            int buf = l / 768, rem = l - buf * 768;
            int row = rem / 12, seg = rem - row * 12;
            int j = j0 + row;
            u32 dst = smb + AVH + (u32)buf * 13312u + (u32)row * 208u + (u32)seg * 16u;
            cpa16(dst, (buf ? vpl : vph) + (size_t)j * 96 + seg * 8, (j < KN) ? 16 : 0);
        }
        CP_COMMIT();
        CP_WAIT0();
        __syncthreads();

        // ---- Q'K'^T -> finished scores: warp does 16 rows x 32 keys ----
        float S[4][4];
        #pragma unroll
        for (int jt = 0; jt < 4; ++jt)
            #pragma unroll
            for (int i = 0; i < 4; ++i) S[jt][i] = 0.f;

        #pragma unroll
        for (int ks = 0; ks < 8; ++ks) {
            u32 ah4[4], al4[4];
            u32 aaddr = smb + AQE_H + (u32)(wr0 + (lane & 15)) * 272u
                      + (u32)(ks * 16 + ((lane >> 4) << 3)) * 2u;
            ldm_x4(ah4, aaddr);
            ldm_x4(al4, aaddr + (AQE_L - AQE_H));
            #pragma unroll
            for (int jt2 = 0; jt2 < 2; ++jt2) {
                u32 addr = smb + AKH
                         + (u32)(jbase + jt2 * 16 + ((lane >> 4) << 3) + (lane & 7)) * 272u
                         + (u32)(ks * 16 + ((lane >> 3) & 1) * 8) * 2u;
                u32 bh4[4], bl4[4];
                ldm_x4(bh4, addr);
                ldm_x4(bl4, addr + (AKL - AKH));
                mma_bf16(S[2 * jt2],     ah4, bh4);
                mma_bf16(S[2 * jt2],     ah4, bl4);
                mma_bf16(S[2 * jt2],     al4, bh4);
                mma_bf16(S[2 * jt2 + 1], ah4, bh4 + 2);
                mma_bf16(S[2 * jt2 + 1], ah4, bl4 + 2);
                mma_bf16(S[2 * jt2 + 1], al4, bh4 + 2);
            }
        }

        // ---- packed fast exp (padded keys self-mask via -50) ----
        #pragma unroll
        for (int jt = 0; jt < 4; ++jt) {
            u64 eA = fexp2(S[jt][0], S[jt][1]);
            u64 eB = fexp2(S[jt][2], S[jt][3]);
            sumA2 = add2(sumA2, eA);
            sumB2 = add2(sumB2, eB);
            float2 fa = u2f(eA), fb = u2f(eB);
            S[jt][0] = fa.x; S[jt][1] = fa.y;
            S[jt][2] = fb.x; S[jt][3] = fb.y;
        }

        // ---- repack S as P a-fragments (hi/lo) ----
        u32 ph[2][4], pl[2][4];
        #pragma unroll
        for (int t = 0; t < 2; ++t) {
            ph[t][0] = pack_hi(S[2 * t][0],     S[2 * t][1],     pl[t][0]);
            ph[t][1] = pack_hi(S[2 * t][2],     S[2 * t][3],     pl[t][1]);
            ph[t][2] = pack_hi(S[2 * t + 1][0], S[2 * t + 1][1], pl[t][2]);
            ph[t][3] = pack_hi(S[2 * t + 1][2], S[2 * t + 1][3], pl[t][3]);
        }

        // ---- P @ V over this warp's 32 keys ----
        #pragma unroll
        for (int kt = 0; kt < 2; ++kt) {
            #pragma unroll
            for (int nt2 = 0; nt2 < 6; ++nt2) {
                u32 addr = smb + AVH
                         + (u32)(jbase + kt * 16 + ((lane >> 3) & 1) * 8 + (lane & 7)) * 208u
                         + (u32)(nt2 * 16 + ((lane >> 4) << 3)) * 2u;
                u32 vh4[4], vl4[4];
                ldm_x4t(vh4, addr);
                ldm_x4t(vl4, addr + (AVL - AVH));
                mma_bf16(O[2 * nt2],     ph[kt], vh4);
                mma_bf16(O[2 * nt2],     ph[kt], vl4);
                mma_bf16(O[2 * nt2],     pl[kt], vh4);
                mma_bf16(O[2 * nt2 + 1], ph[kt], vh4 + 2);
                mma_bf16(O[2 * nt2 + 1], ph[kt], vl4 + 2);
                mma_bf16(O[2 * nt2 + 1], pl[kt], vh4 + 2);
            }
        }
        __syncthreads();
    }

    // ---- sums: horizontal + quad reduce ----
    float2 sa = u2f(sumA2), sb = u2f(sumB2);
    float sumA = sa.x + sa.y;
    float sumB = sb.x + sb.y;
    sumA += __shfl_xor_sync(0xffffffffu, sumA, 1);
    sumA += __shfl_xor_sync(0xffffffffu, sumA, 2);
    sumB += __shfl_xor_sync(0xffffffffu, sumB, 1);
    sumB += __shfl_xor_sync(0xffffffffu, sumB, 2);

    // ---- cross-warp (jhalf) O + sum reduction via smem (QE region dead) ----
    int gc = 2 * (lane & 3);
    if (jhalf == 1) {
        #pragma unroll
        for (int nt = 0; nt < 12; ++nt) {
            int col = nt * 8 + gc;
            *(float2*)&Obuf[(wr0 + gr) * 96 + col]     = make_float2(O[nt][0], O[nt][1]);
            *(float2*)&Obuf[(wr0 + 8 + gr) * 96 + col] = make_float2(O[nt][2], O[nt][3]);
        }
        if ((lane & 3) == 0) {
            ssum1[wr0 + gr] = sumA;
            ssum1[wr0 + 8 + gr] = sumB;
        }
    }
    __syncthreads();
    if (jhalf == 0) {
        sumA += ssum1[wr0 + gr];
        sumB += ssum1[wr0 + 8 + gr];
        float riA = 1.f / sumA;
        float riB = 1.f / sumB;
        int b = bh >> 1, head = bh & 1;
        #pragma unroll
        for (int nt = 0; nt < 12; ++nt) {
            int col = nt * 8 + gc;
            float2 oA = *(const float2*)&Obuf[(wr0 + gr) * 96 + col];
            float2 oB = *(const float2*)&Obuf[(wr0 + 8 + gr) * 96 + col];
            if (qrA < QN) {
                float2 qv = *(const float2*)&qp[(size_t)qrA * 96 + col];
                float2 o = make_float2((O[nt][0] + oA.x) * riA + qv.x,
                                       (O[nt][1] + oA.y) * riA + qv.y);
                split_store(g_aoh, g_aol,
                            ((size_t)(b * QN + qrA)) * 192 + head * 96 + col, o);
            }
            if (qrB < QN) {
                float2 qv = *(const float2*)&qp[(size_t)qrB * 96 + col];
                float2 o = make_float2((O[nt][2] + oB.x) * riB + qv.x,
                                       (O[nt][3] + oB.y) * riB + qv.y);
                split_store(g_aoh, g_aol,
                            ((size_t)(b * QN + qrB)) * 192 + head * 96 + col, o);
            }
        }
    }
}

// ---------------- launch ----------------
extern "C" void kernel_launch(void* const* d_in, const int* in_sizes, int n_in,
                              void* d_out, int out_size)
{
    const float* x      = (const float*)d_in[0];
    const float* qkv_w  = (const float*)d_in[1];
    const float* qkv_b  = (const float*)d_in[2];
    const float* proj_w = (const float*)d_in[3];
    const float* proj_b = (const float*)d_in[4];
    const float* pq_w   = (const float*)d_in[5];
    const float* nq_g   = (const float*)d_in[6];
    const float* nq_b   = (const float*)d_in[7];
    const float* pk_w   = (const float*)d_in[8];
    const float* nk_g   = (const float*)d_in[9];
    const float* nk_b   = (const float*)d_in[10];
    const float* pv_w   = (const float*)d_in[11];
    const float* nv_g   = (const float*)d_in[12];
    const float* nv_b   = (const float*)d_in[13];
    const float* rph    = (const float*)d_in[14];
    const float* rpw    = (const float*)d_in[15];
    const float* rpt    = (const float*)d_in[16];

    int B = in_sizes[0] / (N_IN * 96);
    if (B > B_MAX) B = B_MAX;
    int M   = B * N_IN;
    int Mkv = B * NKV;
    int nbQ  = (M + 127) / 128;
    int nbKV = (Mkv + 127) / 128;

    cudaFuncSetAttribute(gemm_bf16, cudaFuncAttributeMaxDynamicSharedMemorySize, GEMM_SMEM);
    cudaFuncSetAttribute(attn_fa2_kernel, cudaFuncAttributeMaxDynamicSharedMemorySize, ATTN_SMEM2);

    int nx = M * 48;
    int totalPairs = nx + 576 * 96 / 2 + 192 * 192 / 2;
    presplit_kernel<<<(totalPairs + 255) / 256, 256>>>(x, qkv_w, proj_w, nx);

    gemm_bf16<<<nbQ + 2 * nbKV, 256, GEMM_SMEM>>>(qkv_b, nullptr, M, Mkv, 96, nbQ, nbKV, 1);

    int nSpatial = B * 2 * QH * QW;
    int nPQ  = nSpatial + B * 2;
    int nPKV = B * 2 * KNP;
    pool_all_kernel<<<nPQ + 2 * nPKV, 96>>>(pq_w, nq_g, nq_b, pk_w, nk_g, nk_b,
                                            pv_w, nv_g, nv_b, nSpatial, nPQ, nPKV);
    attn_fa2_kernel<<<dim3((QN + AROWS - 1) / AROWS, B * 2), 256, ATTN_SMEM2>>>(rph, rpw, rpt);

    gemm_bf16<<<(B * QN + 127) / 128, 256, GEMM_SMEM>>>(proj_b, (float*)d_out,
                                                        B * QN, 0, 192, 0, 0, 0);
}

// round 17
// speedup vs baseline: 1.0554x; 1.0272x over previous
#include <cuda_runtime.h>
#include <cuda_bf16.h>
#include <cuda_fp16.h>
#include <math.h>

typedef unsigned long long u64;
typedef unsigned int u32;

#define B_MAX 4
#define N_IN 25089      // 1 + 8*56*56
#define T_IN 8
#define H_IN 56
#define W_IN 56
#define QT 8
#define QH 28
#define QW 28
#define QN 6273         // 1 + 8*28*28
#define KT 8
#define KH 7
#define KW 7
#define KN 393          // 1 + 8*7*7
#define KNP 448         // padded key count
#define NKV 3201        // 1 + 8*20*20 gathered tokens per batch
#define ATTN_SCALE 0.102062072615965745f   // 1/sqrt(96)

// ---------------- scratch (device globals; no allocation) ----------------
__device__ float g_q [(size_t)B_MAX * N_IN * 192];
__device__ float g_k [(size_t)B_MAX * NKV * 192];
__device__ float g_v [(size_t)B_MAX * NKV * 192];
__device__ float g_qp[(size_t)B_MAX * 2 * QN * 96];
// bf16 hi/lo pre-split tensors
__device__ __nv_bfloat16 g_xh[(size_t)B_MAX * N_IN * 96];
__device__ __nv_bfloat16 g_xl[(size_t)B_MAX * N_IN * 96];
__device__ __nv_bfloat16 g_wh[576 * 96];
__device__ __nv_bfloat16 g_wl[576 * 96];
__device__ __nv_bfloat16 g_pwh[192 * 192];
__device__ __nv_bfloat16 g_pwl[192 * 192];
__device__ __nv_bfloat16 g_aoh[(size_t)B_MAX * QN * 192];
__device__ __nv_bfloat16 g_aol[(size_t)B_MAX * QN * 192];
// pooled q pre-split (unscaled)
__device__ __nv_bfloat16 g_qph[(size_t)B_MAX * 2 * QN * 96];
__device__ __nv_bfloat16 g_qpl[(size_t)B_MAX * 2 * QN * 96];
// extended pooled K (128 cols: 96 scaled ch + 22 onehot + mask + (-8)col + pad)
__device__ __nv_bfloat16 g_keh[(size_t)B_MAX * 2 * KNP * 128];
__device__ __nv_bfloat16 g_kel[(size_t)B_MAX * 2 * KNP * 128];
// pooled V as fp16 hi/lo
__device__ __half g_vph[(size_t)B_MAX * 2 * KN * 96];
__device__ __half g_vpl[(size_t)B_MAX * 2 * KN * 96];

// ---------------- helpers ----------------
__device__ __forceinline__ int hw_from_idx(int i) {
    return (i < 2) ? i : 7 + ((i - 2) / 3) * 8 + ((i - 2) % 3);
}
__device__ __forceinline__ u32 smem_u32(const void* p) {
    u32 a;
    asm("{ .reg .u64 t; cvta.to.shared.u64 t, %1; cvt.u32.u64 %0, t; }" : "=r"(a) : "l"(p));
    return a;
}
__device__ __forceinline__ u64 fma2o(u64 a, u64 b, u64 c) {
    u64 d; asm("fma.rn.f32x2 %0, %1, %2, %3;" : "=l"(d) : "l"(a), "l"(b), "l"(c)); return d;
}
__device__ __forceinline__ u64 add2(u64 a, u64 b) {
    u64 d; asm("add.rn.f32x2 %0, %1, %2;" : "=l"(d) : "l"(a), "l"(b)); return d;
}
__device__ __forceinline__ u64 mul2(u64 a, u64 b) {
    u64 d; asm("mul.rn.f32x2 %0, %1, %2;" : "=l"(d) : "l"(a), "l"(b)); return d;
}
__device__ __forceinline__ u64 dupf(float v) {
    u64 r; asm("mov.b64 %0, {%1, %1};" : "=l"(r) : "f"(v)); return r;
}
__device__ __forceinline__ float2 u2f(u64 v) {
    float2 r; asm("mov.b64 {%0, %1}, %2;" : "=f"(r.x), "=f"(r.y) : "l"(v)); return r;
}
__device__ __forceinline__ u64 pk2(float a, float b) {
    u64 r; asm("mov.b64 %0, {%1, %2};" : "=l"(r) : "f"(a), "f"(b)); return r;
}
// packed fast exp: e^x for two lanes, poly deg-4, rel err ~4e-5
__device__ __forceinline__ u64 fexp2(float a, float b) {
    u64 x2 = pk2(a, b);
    u64 t2 = fma2o(x2, dupf(1.4426950408889634f), dupf(12582912.f));
    u64 n2 = add2(t2, dupf(-12582912.f));
    u64 r2 = fma2o(n2, dupf(-0.6931471805599453f), x2);
    u64 p2 = fma2o(r2, dupf(4.1666667e-2f), dupf(1.6666667e-1f));
    p2 = fma2o(p2, r2, dupf(0.5f));
    p2 = fma2o(p2, r2, dupf(1.0f));
    p2 = fma2o(p2, r2, dupf(1.0f));
    u32 tl = (u32)t2, th = (u32)(t2 >> 32);
    u32 sl = (tl << 23) + 0x3f800000u;
    u32 sh = (th << 23) + 0x3f800000u;
    u64 s2 = ((u64)sh << 32) | (u64)sl;
    return mul2(p2, s2);
}

// ---------------- mma.sync helpers ----------------
__device__ __forceinline__ void ldm_x4(u32* r, u32 addr) {
    asm volatile("ldmatrix.sync.aligned.m8n8.x4.shared.b16 {%0,%1,%2,%3}, [%4];"
        : "=r"(r[0]), "=r"(r[1]), "=r"(r[2]), "=r"(r[3]) : "r"(addr));
}
__device__ __forceinline__ void ldm_x4t(u32* r, u32 addr) {
    asm volatile("ldmatrix.sync.aligned.m8n8.x4.trans.shared.b16 {%0,%1,%2,%3}, [%4];"
        : "=r"(r[0]), "=r"(r[1]), "=r"(r[2]), "=r"(r[3]) : "r"(addr));
}
__device__ __forceinline__ void mma_bf16(float* c, const u32* a, const u32* b) {
    asm volatile("mma.sync.aligned.m16n8k16.row.col.f32.bf16.bf16.f32 "
        "{%0,%1,%2,%3}, {%4,%5,%6,%7}, {%8,%9}, {%0,%1,%2,%3};"
        : "+f"(c[0]), "+f"(c[1]), "+f"(c[2]), "+f"(c[3])
        : "r"(a[0]), "r"(a[1]), "r"(a[2]), "r"(a[3]), "r"(b[0]), "r"(b[1]));
}
__device__ __forceinline__ void mma_fp16(float* c, const u32* a, const u32* b) {
    asm volatile("mma.sync.aligned.m16n8k16.row.col.f32.f16.f16.f32 "
        "{%0,%1,%2,%3}, {%4,%5,%6,%7}, {%8,%9}, {%0,%1,%2,%3};"
        : "+f"(c[0]), "+f"(c[1]), "+f"(c[2]), "+f"(c[3])
        : "r"(a[0]), "r"(a[1]), "r"(a[2]), "r"(a[3]), "r"(b[0]), "r"(b[1]));
}
__device__ __forceinline__ void split_store(__nv_bfloat16* hi, __nv_bfloat16* lo,
                                            size_t idx, float2 v) {
    __nv_bfloat162 h = __floats2bfloat162_rn(v.x, v.y);
    __nv_bfloat162 l = __floats2bfloat162_rn(v.x - __bfloat162float(h.x),
                                             v.y - __bfloat162float(h.y));
    *(__nv_bfloat162*)(hi + idx) = h;
    *(__nv_bfloat162*)(lo + idx) = l;
}
__device__ __forceinline__ u32 pkh2(float a, float b) {
    __half2 h = __floats2half2_rn(a, b);
    return *(u32*)&h;
}
__device__ __forceinline__ void cpa16(u32 dst, const void* src, int srcsize) {
    asm volatile("cp.async.cg.shared.global [%0], [%1], 16, %2;"
        :: "r"(dst), "l"(src), "r"(srcsize));
}
#define CP_COMMIT() asm volatile("cp.async.commit_group;" ::: "memory")
#define CP_WAIT0()  asm volatile("cp.async.wait_group 0;" ::: "memory")
#define CP_WAIT1()  asm volatile("cp.async.wait_group 1;" ::: "memory")

// ---------------- presplit: x / qkv_w / proj_w -> bf16 hi/lo ----------------
__global__ void presplit_kernel(const float* __restrict__ x,
                                const float* __restrict__ qkv_w,
                                const float* __restrict__ proj_w, int nx)
{
    int i = blockIdx.x * 256 + threadIdx.x;
    const int nqkv = 576 * 96 / 2;
    const int nproj = 192 * 192 / 2;
    const float* src;
    __nv_bfloat16 *dh, *dl;
    int off;
    if (i < nx)                   { src = x;      dh = g_xh;  dl = g_xl;  off = i; }
    else if (i < nx + nqkv)       { src = qkv_w;  dh = g_wh;  dl = g_wl;  off = i - nx; }
    else if (i < nx + nqkv + nproj) { src = proj_w; dh = g_pwh; dl = g_pwl; off = i - nx - nqkv; }
    else return;
    float2 v = ((const float2*)src)[off];
    split_store(dh, dl, (size_t)(2 * off), v);
}

// ============================================================================
// cp.async double-buffered bf16 tensor-core GEMM (unchanged)
// ============================================================================
#define STG_BYTES 51200
#define STG_AL 10240
#define STG_B  20480
#define STG_BL 15360
#define GEMM_SMEM (2 * STG_BYTES)

__global__ void __launch_bounds__(256) gemm_bf16(
    const float* __restrict__ bias_all, float* __restrict__ outp,
    int Mq, int Mkv, int K, int nbQ, int nbKV, int fused)
{
    extern __shared__ char sm[];
    u32 smb = smem_u32(sm);

    int tid = threadIdx.x;
    int warp = tid >> 5, lane = tid & 31;
    int rm = (warp & 3) * 32;
    int cn = (warp >> 2) * 96;

    const __nv_bfloat16 *Asrc_h, *Asrc_l, *Bsrc_h, *Bsrc_l;
    const float* bp;
    float* out;
    int r0, Mloc;
    bool gather = false;
    if (!fused) {
        Asrc_h = g_aoh; Asrc_l = g_aol; Bsrc_h = g_pwh; Bsrc_l = g_pwl;
        bp = bias_all; out = outp; r0 = blockIdx.x * 128; Mloc = Mq;
    } else if ((int)blockIdx.x < nbQ) {
        Asrc_h = g_xh; Asrc_l = g_xl; Bsrc_h = g_wh; Bsrc_l = g_wl;
        bp = bias_all; out = (float*)g_q; r0 = blockIdx.x * 128; Mloc = Mq;
    } else {
        int t = blockIdx.x - nbQ;
        int sel = t / nbKV, bx2 = t - sel * nbKV;
        gather = true;
        Asrc_h = g_xh; Asrc_l = g_xl;
        Bsrc_h = g_wh + (size_t)(1 + sel) * 192 * 96;
        Bsrc_l = g_wl + (size_t)(1 + sel) * 192 * 96;
        bp = bias_all + (1 + sel) * 192;
        out = sel ? (float*)g_v : (float*)g_k;
        r0 = bx2 * 128; Mloc = Mkv;
    }

    size_t aoff[4];
    int asz[4];
    #pragma unroll
    for (int k4 = 0; k4 < 4; ++k4) {
        int l = tid + k4 * 256;
        int row = l >> 3;
        int r = r0 + row;
        if (r < Mloc) {
            asz[k4] = 16;
            if (gather) {
                int b = r / NKV, ci = r - b * NKV;
                int n = 0;
                if (ci > 0) {
                    int cc = ci - 1;
                    int it = cc / 400, rem = cc - it * 400;
                    int h = hw_from_idx(rem / 20), wv = hw_from_idx(rem % 20);
                    n = 1 + (it * H_IN + h) * W_IN + wv;
                }
                aoff[k4] = ((size_t)b * N_IN + n) * 96;
            } else {
                aoff[k4] = (size_t)r * K;
            }
        } else { aoff[k4] = 0; asz[k4] = 0; }
    }

    float C[2][12][4];
    #pragma unroll
    for (int mt = 0; mt < 2; ++mt)
        #pragma unroll
        for (int nt = 0; nt < 12; ++nt)
            #pragma unroll
            for (int i = 0; i < 4; ++i) C[mt][nt][i] = 0.f;

    int nch = K / 32;

    #define ISSUE_CHUNK(c_, st_) do {                                          \
        int kc = (c_) * 32;                                                    \
        u32 sb = smb + (st_) * STG_BYTES;                                      \
        _Pragma("unroll")                                                      \
        for (int k4 = 0; k4 < 4; ++k4) {                                       \
            int l = tid + k4 * 256;                                            \
            int row = l >> 3, hl = (l >> 2) & 1, seg = l & 3;                  \
            u32 dst = sb + hl * STG_AL + (u32)row * 80u + (u32)seg * 16u;      \
            const __nv_bfloat16* s0 = hl ? Asrc_l : Asrc_h;                    \
            cpa16(dst, s0 + aoff[k4] + kc + seg * 8, asz[k4]);                 \
        }                                                                      \
        _Pragma("unroll")                                                      \
        for (int k6 = 0; k6 < 6; ++k6) {                                       \
            int l = tid + k6 * 256;                                            \
            int row = l >> 3, hl = (l >> 2) & 1, seg = l & 3;                  \
            u32 dst = sb + STG_B + hl * STG_BL + (u32)row * 80u + (u32)seg * 16u; \
            const __nv_bfloat16* s0 = hl ? Bsrc_l : Bsrc_h;                    \
            cpa16(dst, s0 + (size_t)row * K + kc + seg * 8, 16);               \
        }                                                                      \
        CP_COMMIT();                                                           \
    } while (0)

    ISSUE_CHUNK(0, 0);

    for (int c = 0; c < nch; ++c) {
        int st = c & 1;
        if (c + 1 < nch) {
            ISSUE_CHUNK(c + 1, st ^ 1);
            CP_WAIT1();
        } else {
            CP_WAIT0();
        }
        __syncthreads();

        u32 sb = smb + st * STG_BYTES;
        #pragma unroll
        for (int ks = 0; ks < 2; ++ks) {
            int k0 = ks * 16;
            u32 ah[2][4], al[2][4];
            #pragma unroll
            for (int mt = 0; mt < 2; ++mt) {
                u32 off = (u32)(rm + mt * 16 + (lane & 15)) * 80u
                        + (u32)(k0 + ((lane >> 4) << 3)) * 2u;
                ldm_x4(ah[mt], sb + off);
                ldm_x4(al[mt], sb + STG_AL + off);
            }
            #pragma unroll
            for (int np = 0; np < 6; ++np) {
                u32 off = (u32)(cn + np * 16 + ((lane >> 4) << 3) + (lane & 7)) * 80u
                        + (u32)(k0 + (((lane >> 3) & 1) << 3)) * 2u;
                u32 bh4[4], bl4[4];
                ldm_x4(bh4, sb + STG_B + off);
                ldm_x4(bl4, sb + STG_B + STG_BL + off);
                #pragma unroll
                for (int mt = 0; mt < 2; ++mt) {
                    mma_bf16(C[mt][2 * np],     ah[mt], bh4);
                    mma_bf16(C[mt][2 * np],     ah[mt], bl4);
                    mma_bf16(C[mt][2 * np],     al[mt], bh4);
                    mma_bf16(C[mt][2 * np + 1], ah[mt], bh4 + 2);
                    mma_bf16(C[mt][2 * np + 1], ah[mt], bl4 + 2);
                    mma_bf16(C[mt][2 * np + 1], al[mt], bh4 + 2);
                }
            }
        }
        __syncthreads();
    }

    int gr = lane >> 2;
    int gc = (lane & 3) * 2;
    #pragma unroll
    for (int mt = 0; mt < 2; ++mt) {
        int row0 = r0 + rm + mt * 16 + gr;
        int row1 = row0 + 8;
        #pragma unroll
        for (int nt = 0; nt < 12; ++nt) {
            int col = cn + nt * 8 + gc;
            float b0 = bp[col], b1 = bp[col + 1];
            if (row0 < Mloc) {
                float2 o = make_float2(C[mt][nt][0] + b0, C[mt][nt][1] + b1);
                *(float2*)&out[(size_t)row0 * 192 + col] = o;
            }
            if (row1 < Mloc) {
                float2 o = make_float2(C[mt][nt][2] + b0, C[mt][nt][3] + b1);
                *(float2*)&out[(size_t)row1 * 192 + col] = o;
            }
        }
    }
}

// ---------------- LN helper (96 threads) ----------------
__device__ __forceinline__ float ln96(float val, const float* gg, const float* bb, int c,
                                      float* p1, float* p2, float* mv)
{
    float s1 = val, s2 = val * val;
    #pragma unroll
    for (int off = 16; off > 0; off >>= 1) {
        s1 += __shfl_xor_sync(0xffffffffu, s1, off);
        s2 += __shfl_xor_sync(0xffffffffu, s2, off);
    }
    int wid = c >> 5, lane = c & 31;
    if (lane == 0) { p1[wid] = s1; p2[wid] = s2; }
    __syncthreads();
    if (c == 0) {
        float t1 = p1[0] + p1[1] + p1[2];
        float t2 = p2[0] + p2[1] + p2[2];
        float mean = t1 / 96.f;
        float var  = t2 / 96.f - mean * mean;
        mv[0] = mean; mv[1] = rsqrtf(var + 1e-5f);
    }
    __syncthreads();
    return (val - mv[0]) * mv[1] * gg[c] + bb[c];
}

// ---------------- merged pool kernel ----------------
__global__ void pool_all_kernel(
    const float* __restrict__ cwq, const float* __restrict__ ggq, const float* __restrict__ bbq,
    const float* __restrict__ cwk, const float* __restrict__ ggk, const float* __restrict__ bbk,
    const float* __restrict__ cwv, const float* __restrict__ ggv, const float* __restrict__ bbv,
    int nSpatial, int nPQ, int nPKV)
{
    __shared__ float p1[3], p2[3], mv[2];
    int bx = blockIdx.x;
    int c = threadIdx.x;

    if (bx < nPQ) {
        int o = bx;
        if (o >= nSpatial) {
            int idx = o - nSpatial;
            int head = idx & 1, b = idx >> 1;
            float val = g_q[((size_t)b * N_IN) * 192 + head * 96 + c];
            float outv = ln96(val, ggq, bbq, c, p1, p2, mv);
            size_t oi = ((size_t)((b * 2 + head) * QN)) * 96 + c;
            g_qp[oi] = outv;
            __nv_bfloat16 h = __float2bfloat16(outv);
            g_qph[oi] = h;
            g_qpl[oi] = __float2bfloat16(outv - __bfloat162float(h));
            return;
        }
        int w2 = o % QW;
        int h2 = (o / QW) % QH;
        int head = (o / (QW * QH)) & 1;
        int b = o / (QW * QH * 2);

        float wreg[27];
        #pragma unroll
        for (int t = 0; t < 27; ++t) wreg[t] = cwq[c * 27 + t];

        float ps[8][3];
        #pragma unroll
        for (int it = 0; it < 8; ++it)
            #pragma unroll
            for (int d = 0; d < 3; ++d) ps[it][d] = 0.f;

        const float* base = g_q + ((size_t)(b * N_IN + 1)) * 192 + head * 96 + c;
        #pragma unroll
        for (int dh = 0; dh < 3; ++dh) {
            int ih = 2 * h2 - 1 + dh;
            if (ih < 0 || ih >= H_IN) continue;
            #pragma unroll
            for (int dw = 0; dw < 3; ++dw) {
                int iw = 2 * w2 - 1 + dw;
                if (iw < 0 || iw >= W_IN) continue;
                float w0 = wreg[(0 * 3 + dh) * 3 + dw];
                float w1 = wreg[(1 * 3 + dh) * 3 + dw];
                float w2r = wreg[(2 * 3 + dh) * 3 + dw];
                #pragma unroll
                for (int it = 0; it < 8; ++it) {
                    int tok = (it * H_IN + ih) * W_IN + iw;
                    float v = base[(size_t)tok * 192];
                    ps[it][0] = fmaf(w0, v, ps[it][0]);
                    ps[it][1] = fmaf(w1, v, ps[it][1]);
                    ps[it][2] = fmaf(w2r, v, ps[it][2]);
                }
            }
        }
        for (int t2 = 0; t2 < QT; ++t2) {
            float s = ps[t2][1];
            if (t2 > 0) s += ps[t2 - 1][0];
            if (t2 < 7) s += ps[t2 + 1][2];
            float outv = ln96(s, ggq, bbq, c, p1, p2, mv);
            int n = 1 + (t2 * QH + h2) * QW + w2;
            size_t oi = ((size_t)((b * 2 + head) * QN) + n) * 96 + c;
            g_qp[oi] = outv;
            __nv_bfloat16 h = __float2bfloat16(outv);
            g_qph[oi] = h;
            g_qpl[oi] = __float2bfloat16(outv - __bfloat162float(h));
            __syncthreads();
        }
        return;
    }

    int t = bx - nPQ;
    int whichV = t / nPKV;
    int o = t - whichV * nPKV;
    const float* cw = whichV ? cwv : cwk;
    const float* gg = whichV ? ggv : ggk;
    const float* bb = whichV ? bbv : bbk;
    int n    = o % KNP;
    int head = (o / KNP) & 1;
    int b    = o / (KNP * 2);
    int bh   = b * 2 + head;

    if (n >= KN) {
        if (whichV) return;
        size_t rb = ((size_t)bh * KNP + n) * 128;
        __nv_bfloat16 z = __float2bfloat16(0.f);
        g_keh[rb + c] = z; g_kel[rb + c] = z;
        if (c < 32) {
            // padded rows: mask col 22 = 1 (adds -50), shift col 23 = 1 (adds -8)
            g_keh[rb + 96 + c] = __float2bfloat16((c == 22 || c == 23) ? 1.f : 0.f);
            g_kel[rb + 96 + c] = z;
        }
        return;
    }

    const float* src = whichV ? g_v : g_k;
    float val;
    if (n == 0) {
        val = src[((size_t)b * NKV) * 192 + head * 96 + c];
    } else {
        int tn  = n - 1;
        int t2  = tn / (KH * KW);
        int rem = tn % (KH * KW);
        int h2  = rem / KW, w2 = rem % KW;
        float s = 0.f;
        #pragma unroll
        for (int dt = 0; dt < 3; ++dt) {
            int it = t2 + dt - 1;
            if (it < 0 || it >= T_IN) continue;
            #pragma unroll
            for (int dh = 0; dh < 3; ++dh) {
                int ih = h2 * 8 + dh - 1;
                if (ih < 0 || ih >= H_IN) continue;
                #pragma unroll
                for (int dw = 0; dw < 3; ++dw) {
                    int iw = w2 * 8 + dw - 1;
                    if (iw < 0 || iw >= W_IN) continue;
                    int hi2 = (ih <= 1) ? ih : 2 + ((ih - 7) >> 3) * 3 + ((ih - 7) & 7);
                    int wi2 = (iw <= 1) ? iw : 2 + ((iw - 7) >> 3) * 3 + ((iw - 7) & 7);
                    int ci = 1 + (it * 20 + hi2) * 20 + wi2;
                    s = fmaf(cw[c * 27 + (dt * 3 + dh) * 3 + dw],
                             src[((size_t)(b * NKV + ci)) * 192 + head * 96 + c], s);
                }
            }
        }
        val = s;
    }
    float outv = ln96(val, gg, bb, c, p1, p2, mv);
    if (whichV) {
        size_t oidx = ((size_t)bh * KN + n) * 96 + c;
        __half h = __float2half(outv);
        g_vph[oidx] = h;
        g_vpl[oidx] = __float2half(outv - __half2float(h));
    } else {
        // fold ATTN_SCALE into K channels
        float sv = outv * ATTN_SCALE;
        size_t rb = ((size_t)bh * KNP + n) * 128;
        __nv_bfloat16 h = __float2bfloat16(sv);
        g_keh[rb + c] = h;
        g_kel[rb + c] = __float2bfloat16(sv - __bfloat162float(h));
        if (c < 32) {
            float ev = 0.f;
            if (n > 0 && c < 22) {
                int kk = n - 1, kt = kk / 49, rm = kk % 49;
                int rh = rm / 7, rw = rm % 7;
                if (c == kt || c == 8 + rh || c == 15 + rw) ev = 1.f;
            }
            if (c == 23) ev = 1.f;   // -8 shift column (all keys incl cls)
            g_keh[rb + 96 + c] = __float2bfloat16(ev);
            g_kel[rb + 96 + c] = __float2bfloat16(0.f);
        }
    }
}

// ============================================================================
// FA2 attention: 256 threads, 8 warps = (m 0-3) x (jhalf 0-1),
// 64 q-rows/block, K'=128 (incl -8 shift col), fp16 single-P PV (2 products)
// ============================================================================
#define AROWS  64
#define AQE_H  0
#define AQE_L  17408
#define AKH    34816
#define AKL    52224
#define AVH    69632
#define AVL    82944
#define ASRX   69632            // [64][34] fp32, phase-1 overlay of V region
#define AOBUF  0                // [64][96] fp32, end overlay of QE region
#define ASSUM  24576            // [64] fp32
#define ATTN_SMEM2 96256

__global__ void __launch_bounds__(256) attn_fa2_kernel(
    const float* __restrict__ rph, const float* __restrict__ rpw,
    const float* __restrict__ rpt)
{
    extern __shared__ char sm[];
    float* srx = (float*)(sm + ASRX);
    __nv_bfloat16* QEh = (__nv_bfloat16*)(sm + AQE_H);
    __nv_bfloat16* QEl = (__nv_bfloat16*)(sm + AQE_L);
    float* Obuf = (float*)(sm + AOBUF);
    float* ssum1 = (float*)(sm + ASSUM);
    u32 smb = smem_u32(sm);

    int tid = threadIdx.x;
    int warp = tid >> 5, lane = tid & 31;
    int wm = warp & 3, jhalf = warp >> 2;
    int gr = lane >> 2;
    int wr0 = wm * 16;
    int jbase = jhalf * 32;
    int bh = blockIdx.y;
    int q0 = blockIdx.x * AROWS;
    const float* qp = g_qp + (size_t)bh * QN * 96;
    const __nv_bfloat16* qsh = g_qph + (size_t)bh * QN * 96;
    const __nv_bfloat16* qsl = g_qpl + (size_t)bh * QN * 96;
    const __nv_bfloat16* keh = g_keh + (size_t)bh * KNP * 128;
    const __nv_bfloat16* kel = g_kel + (size_t)bh * KNP * 128;
    const __half* vph = g_vph + (size_t)bh * KN * 96;
    const __half* vpl = g_vpl + (size_t)bh * KN * 96;

    // ---- phase 1: stage pre-split Q into QE cols 0..95 ----
    #pragma unroll
    for (int k6 = 0; k6 < 6; ++k6) {
        int l = tid + k6 * 256;          // 64 rows x 12 segs x 2 bufs = 1536
        int buf = l >= 768;
        int rem = l - buf * 768;
        int row = rem / 12, seg = rem - row * 12;
        int qr = q0 + row;
        u32 dst = smb + (buf ? AQE_L : AQE_H) + (u32)row * 272u + (u32)seg * 16u;
        cpa16(dst, (buf ? qsl : qsh) + (size_t)qr * 96 + seg * 8, (qr < QN) ? 16 : 0);
    }
    CP_COMMIT();

    // ---- rel-pos dots from fp32 g_qp into srx ----
    for (int idx = tid; idx < AROWS * 22; idx += 256) {
        int qi = idx / 22, r = idx - qi * 22;
        int qr = q0 + qi;
        float s = 0.f;
        if (qr > 0 && qr < QN) {
            int tok = qr - 1;
            int tq = tok / (QH * QW);
            int hq = (tok / QW) % QH;
            int wq = tok % QW;
            const float* tab;
            if (r < 8)       tab = rpt + (size_t)(tq - r + 7) * 96;
            else if (r < 15) tab = rph + (size_t)(hq - 4 * (r - 8) + 24) * 96;
            else             tab = rpw + (size_t)(wq - 4 * (r - 15) + 24) * 96;
            const float* qrow = qp + (size_t)qr * 96;
            u64 acc = 0ull;
            #pragma unroll 8
            for (int k = 0; k < 96; k += 2)
                acc = fma2o(*(const u64*)&qrow[k], *(const u64*)&tab[k], acc);
            float2 pr = u2f(acc);
            s = pr.x + pr.y;
        }
        srx[qi * 34 + r] = s;
    }
    CP_WAIT0();
    __syncthreads();

    // ---- fill QE ext cols 96..127 (srel, -50 mask, -8 shift, zeros) ----
    for (int l = tid; l < AROWS * 16; l += 256) {
        int row = l >> 4, cp = l & 15;
        int col = 96 + 2 * cp;
        int r0c = 2 * cp, r1c = r0c + 1;
        float2 v;
        v.x = (r0c < 22) ? srx[row * 34 + r0c]
             : ((r0c == 22) ? -50.f : ((r0c == 23) ? -8.f : 0.f));
        v.y = (r1c < 22) ? srx[row * 34 + r1c]
             : ((r1c == 22) ? -50.f : ((r1c == 23) ? -8.f : 0.f));
        split_store(QEh, QEl, (size_t)row * 136 + col, v);
    }
    __syncthreads();   // QE built; srx dead -> K'/V regions free

    int qrA = q0 + wr0 + gr;
    int qrB = qrA + 8;

    float O[12][4];
    #pragma unroll
    for (int nt = 0; nt < 12; ++nt)
        #pragma unroll
        for (int i = 0; i < 4; ++i) O[nt][i] = 0.f;
    u64 sumA2 = 0ull, sumB2 = 0ull;

    for (int ch = 0; ch < 7; ++ch) {
        int j0 = ch * 64;
        // stage K' (64 x 272B x2) and V (64 x 208B x2, fp16)
        #pragma unroll
        for (int k8 = 0; k8 < 8; ++k8) {
            int l = tid + k8 * 256;
            int buf = l >> 10, rem = l & 1023;
            int row = rem >> 4, seg = rem & 15;
            u32 dst = smb + AKH + (u32)buf * 17408u + (u32)row * 272u + (u32)seg * 16u;
            cpa16(dst, (buf ? kel : keh) + ((size_t)(j0 + row)) * 128 + seg * 8, 16);
        }
        #pragma unroll
        for (int k6 = 0; k6 < 6; ++k6) {
            int l = tid + k6 * 256;
            int buf = l / 768, rem = l - buf * 768;
            int row = rem / 12, seg = rem - row * 12;
            int j = j0 + row;
            u32 dst = smb + AVH + (u32)buf * 13312u + (u32)row * 208u + (u32)seg * 16u;
            cpa16(dst, (buf ? vpl : vph) + (size_t)j * 96 + seg * 8, (j < KN) ? 16 : 0);
        }
        CP_COMMIT();
        CP_WAIT0();
        __syncthreads();

        // ---- Q'K'^T -> finished scores (pre-shifted by -8) ----
        float S[4][4];
        #pragma unroll
        for (int jt = 0; jt < 4; ++jt)
            #pragma unroll
            for (int i = 0; i < 4; ++i) S[jt][i] = 0.f;

        #pragma unroll
        for (int ks = 0; ks < 8; ++ks) {
            u32 ah4[4], al4[4];
            u32 aaddr = smb + AQE_H + (u32)(wr0 + (lane & 15)) * 272u
                      + (u32)(ks * 16 + ((lane >> 4) << 3)) * 2u;
            ldm_x4(ah4, aaddr);
            ldm_x4(al4, aaddr + (AQE_L - AQE_H));
            #pragma unroll
            for (int jt2 = 0; jt2 < 2; ++jt2) {
                u32 addr = smb + AKH
                         + (u32)(jbase + jt2 * 16 + ((lane >> 4) << 3) + (lane & 7)) * 272u
                         + (u32)(ks * 16 + ((lane >> 3) & 1) * 8) * 2u;
                u32 bh4[4], bl4[4];
                ldm_x4(bh4, addr);
                ldm_x4(bl4, addr + (AKL - AKH));
                mma_bf16(S[2 * jt2],     ah4, bh4);
                mma_bf16(S[2 * jt2],     ah4, bl4);
                mma_bf16(S[2 * jt2],     al4, bh4);
                mma_bf16(S[2 * jt2 + 1], ah4, bh4 + 2);
                mma_bf16(S[2 * jt2 + 1], ah4, bl4 + 2);
                mma_bf16(S[2 * jt2 + 1], al4, bh4 + 2);
            }
        }

        // ---- packed fast exp (scores pre-shifted; padded keys self-mask) ----
        #pragma unroll
        for (int jt = 0; jt < 4; ++jt) {
            u64 eA = fexp2(S[jt][0], S[jt][1]);
            u64 eB = fexp2(S[jt][2], S[jt][3]);
            sumA2 = add2(sumA2, eA);
            sumB2 = add2(sumB2, eB);
            float2 fa = u2f(eA), fb = u2f(eB);
            S[jt][0] = fa.x; S[jt][1] = fa.y;
            S[jt][2] = fb.x; S[jt][3] = fb.y;
        }

        // ---- pack P as single fp16 a-fragments ----
        u32 ph[2][4];
        #pragma unroll
        for (int t = 0; t < 2; ++t) {
            ph[t][0] = pkh2(S[2 * t][0],     S[2 * t][1]);
            ph[t][1] = pkh2(S[2 * t][2],     S[2 * t][3]);
            ph[t][2] = pkh2(S[2 * t + 1][0], S[2 * t + 1][1]);
            ph[t][3] = pkh2(S[2 * t + 1][2], S[2 * t + 1][3]);
        }

        // ---- P @ V: 2 products (P fp16 single x V fp16 hi/lo) ----
        #pragma unroll
        for (int kt = 0; kt < 2; ++kt) {
            #pragma unroll
            for (int nt2 = 0; nt2 < 6; ++nt2) {
                u32 addr = smb + AVH
                         + (u32)(jbase + kt * 16 + ((lane >> 3) & 1) * 8 + (lane & 7)) * 208u
                         + (u32)(nt2 * 16 + ((lane >> 4) << 3)) * 2u;
                u32 vh4[4], vl4[4];
                ldm_x4t(vh4, addr);
                ldm_x4t(vl4, addr + (AVL - AVH));
                mma_fp16(O[2 * nt2],     ph[kt], vh4);
                mma_fp16(O[2 * nt2],     ph[kt], vl4);
                mma_fp16(O[2 * nt2 + 1], ph[kt], vh4 + 2);
                mma_fp16(O[2 * nt2 + 1], ph[kt], vl4 + 2);
            }
        }
        __syncthreads();
    }

    // ---- sums: horizontal + quad reduce ----
    float2 sa = u2f(sumA2), sb = u2f(sumB2);
    float sumA = sa.x + sa.y;
    float sumB = sb.x + sb.y;
    sumA += __shfl_xor_sync(0xffffffffu, sumA, 1);
    sumA += __shfl_xor_sync(0xffffffffu, sumA, 2);
    sumB += __shfl_xor_sync(0xffffffffu, sumB, 1);
    sumB += __shfl_xor_sync(0xffffffffu, sumB, 2);

    // ---- cross-warp (jhalf) O + sum reduction via smem (QE region dead) ----
    int gc = 2 * (lane & 3);
    if (jhalf == 1) {
        #pragma unroll
        for (int nt = 0; nt < 12; ++nt) {
            int col = nt * 8 + gc;
            *(float2*)&Obuf[(wr0 + gr) * 96 + col]     = make_float2(O[nt][0], O[nt][1]);
            *(float2*)&Obuf[(wr0 + 8 + gr) * 96 + col] = make_float2(O[nt][2], O[nt][3]);
        }
        if ((lane & 3) == 0) {
            ssum1[wr0 + gr] = sumA;
            ssum1[wr0 + 8 + gr] = sumB;
        }
    }
    __syncthreads();
    if (jhalf == 0) {
        sumA += ssum1[wr0 + gr];
        sumB += ssum1[wr0 + 8 + gr];
        float riA = 1.f / sumA;
        float riB = 1.f / sumB;
        int b = bh >> 1, head = bh & 1;
        #pragma unroll
        for (int nt = 0; nt < 12; ++nt) {
            int col = nt * 8 + gc;
            float2 oA = *(const float2*)&Obuf[(wr0 + gr) * 96 + col];
            float2 oB = *(const float2*)&Obuf[(wr0 + 8 + gr) * 96 + col];
            if (qrA < QN) {
                float2 qv = *(const float2*)&qp[(size_t)qrA * 96 + col];
                float2 o = make_float2((O[nt][0] + oA.x) * riA + qv.x,
                                       (O[nt][1] + oA.y) * riA + qv.y);
                split_store(g_aoh, g_aol,
                            ((size_t)(b * QN + qrA)) * 192 + head * 96 + col, o);
            }
            if (qrB < QN) {
                float2 qv = *(const float2*)&qp[(size_t)qrB * 96 + col];
                float2 o = make_float2((O[nt][2] + oB.x) * riB + qv.x,
                                       (O[nt][3] + oB.y) * riB + qv.y);
                split_store(g_aoh, g_aol,
                            ((size_t)(b * QN + qrB)) * 192 + head * 96 + col, o);
            }
        }
    }
}

// ---------------- launch ----------------
extern "C" void kernel_launch(void* const* d_in, const int* in_sizes, int n_in,
                              void* d_out, int out_size)
{
    const float* x      = (const float*)d_in[0];
    const float* qkv_w  = (const float*)d_in[1];
    const float* qkv_b  = (const float*)d_in[2];
    const float* proj_w = (const float*)d_in[3];
    const float* proj_b = (const float*)d_in[4];
    const float* pq_w   = (const float*)d_in[5];
    const float* nq_g   = (const float*)d_in[6];
    const float* nq_b   = (const float*)d_in[7];
    const float* pk_w   = (const float*)d_in[8];
    const float* nk_g   = (const float*)d_in[9];
    const float* nk_b   = (const float*)d_in[10];
    const float* pv_w   = (const float*)d_in[11];
    const float* nv_g   = (const float*)d_in[12];
    const float* nv_b   = (const float*)d_in[13];
    const float* rph    = (const float*)d_in[14];
    const float* rpw    = (const float*)d_in[15];
    const float* rpt    = (const float*)d_in[16];

    int B = in_sizes[0] / (N_IN * 96);
    if (B > B_MAX) B = B_MAX;
    int M   = B * N_IN;
    int Mkv = B * NKV;
    int nbQ  = (M + 127) / 128;
    int nbKV = (Mkv + 127) / 128;

    cudaFuncSetAttribute(gemm_bf16, cudaFuncAttributeMaxDynamicSharedMemorySize, GEMM_SMEM);
    cudaFuncSetAttribute(attn_fa2_kernel, cudaFuncAttributeMaxDynamicSharedMemorySize, ATTN_SMEM2);

    int nx = M * 48;
    int totalPairs = nx + 576 * 96 / 2 + 192 * 192 / 2;
    presplit_kernel<<<(totalPairs + 255) / 256, 256>>>(x, qkv_w, proj_w, nx);

    gemm_bf16<<<nbQ + 2 * nbKV, 256, GEMM_SMEM>>>(qkv_b, nullptr, M, Mkv, 96, nbQ, nbKV, 1);

    int nSpatial = B * 2 * QH * QW;
    int nPQ  = nSpatial + B * 2;
    int nPKV = B * 2 * KNP;
    pool_all_kernel<<<nPQ + 2 * nPKV, 96>>>(pq_w, nq_g, nq_b, pk_w, nk_g, nk_b,
                                            pv_w, nv_g, nv_b, nSpatial, nPQ, nPKV);
    attn_fa2_kernel<<<dim3((QN + AROWS - 1) / AROWS, B * 2), 256, ATTN_SMEM2>>>(rph, rpw, rpt);

    gemm_bf16<<<(B * QN + 127) / 128, 256, GEMM_SMEM>>>(proj_b, (float*)d_out,
                                                        B * QN, 0, 192, 0, 0, 0);
}